// round 10
// baseline (speedup 1.0000x reference)
#include <cuda_runtime.h>
#include <cstdint>

#define BB 128
#define TT 256
#define II 64
#define HH 1024
#define OO 64
#define NCTA 148

#if defined(__CUDA_ARCH_FEAT_SM103_ALL) || defined(__CUDA_ARCH_SPECIFIC__)
#define HAS_TCGEN05 1
#else
#define HAS_TCGEN05 0
#endif

// idesc: dtype=F32(1<<4), atype=TF32(2<<7), btype=TF32(2<<10), N/8=8<<17, M/16=8<<24
#define IDESC_TF32 0x8100910u

// smem: [0]=tmem ptr, [8]=mbar0, [16]=mbar1
// buffer b at 1024 + b*98304: Ahi +0 (32KB), Alo +32768 (32KB),
//                             Bhi +65536 (16KB), Blo +81920 (16KB)
#define SMEM_BYTES 197632

// ---------------- persistent device globals ----------------
__device__ float bufX[TT * BB * II];   // x as [t][b][i]
__device__ float bufH1[BB * HH];       // h1 [b][j]
__device__ float bufH2[BB * HH];       // h2 [b][j]
__device__ float g_u[BB * HH];         // gate [b][j]
__device__ float partA[9 * BB * HH];   // split-K partials, phases A/B [s][b][j]
__device__ float partC[8 * BB * HH];   // split-K partials, gate phase [s][b][j]
__device__ float partH[4 * BB * 128];  // head partials [s][b][o(128)]
__device__ volatile unsigned g_flags[NCTA * 32];  // barrier flags, 128B stride

// ---------------------------------------------------------------------------
__global__ void k_init() {
    int i = blockIdx.x * blockDim.x + threadIdx.x;
    if (i < NCTA * 32) g_flags[i] = 0u;
    if (i < BB * HH) { bufH1[i] = 0.f; bufH2[i] = 0.f; g_u[i] = 1.f; }
}

__global__ void k_prepx(const float* __restrict__ x) {
    int idx = blockIdx.x * blockDim.x + threadIdx.x;
    if (idx < TT * BB * II) {
        int t = idx / (BB * II);
        int r = idx - t * (BB * II);
        int b = r >> 6, i = r & 63;
        bufX[idx] = x[((size_t)b * TT + t) * II + i];
    }
}

// ---------------------------------------------------------------------------
__device__ __forceinline__ uint32_t cvta_s(const void* p) {
    uint32_t a;
    asm("{ .reg .u64 t; cvta.to.shared.u64 t, %1; cvt.u32.u64 %0, t; }"
        : "=r"(a) : "l"(p));
    return a;
}

__device__ __forceinline__ bool elect1() {
    uint32_t p;
    asm volatile("{ .reg .pred p; elect.sync _|p, 0xFFFFFFFF; selp.b32 %0, 1, 0, p; }"
                 : "=r"(p));
    return p != 0;
}

__device__ __forceinline__ uint64_t sdesc(uint32_t addr) {
    // SW128 (2<<61) | version(1<<46) | SBO=64<<32 | LBO=1<<16
    return 0x4000404000010000ull | ((uint64_t)(addr >> 4) & 0x3FFF);
}

__device__ __forceinline__ void mbar_wait(uint32_t mbar, uint32_t parity) {
    asm volatile(
        "{\n\t.reg .pred P;\n\t"
        "WL%=:\n\t"
        "mbarrier.try_wait.parity.acquire.cta.shared::cta.b64 P, [%0], %1, 0x989680;\n\t"
        "@!P bra WL%=;\n\t}"
        :: "r"(mbar), "r"(parity) : "memory");
}

// Distributed-flag grid barrier: per-CTA release store + parallel poll.
__device__ __forceinline__ void gsync(unsigned &epoch, int u, int tid) {
    __syncthreads();
    epoch++;
    __threadfence();                         // release: data before flag
    if (tid == 0) g_flags[u * 32] = epoch;
    for (int i = tid; i < NCTA; i += 128)
        while (g_flags[i * 32] < epoch) { }
    __syncthreads();
    __threadfence();                         // acquire: drop stale L1 lines
}

// exact hi/lo split: hi = tf32 truncation (exact), lo = x - hi (exact)
__device__ __forceinline__ void split_f4(float4 v, float4 &hi, float4 &lo) {
    hi.x = __uint_as_float(__float_as_uint(v.x) & 0xFFFFE000u); lo.x = v.x - hi.x;
    hi.y = __uint_as_float(__float_as_uint(v.y) & 0xFFFFE000u); lo.y = v.y - hi.y;
    hi.z = __uint_as_float(__float_as_uint(v.z) & 0xFFFFE000u); lo.z = v.z - hi.z;
    hi.w = __uint_as_float(__float_as_uint(v.w) & 0xFFFFE000u); lo.w = v.w - hi.w;
}

#if HAS_TCGEN05
#define LDTM32(r, a) \
    asm volatile( \
        "tcgen05.ld.sync.aligned.32x32b.x32.b32 " \
        "{%0, %1, %2, %3, %4, %5, %6, %7, " \
        " %8, %9, %10, %11, %12, %13, %14, %15, " \
        " %16, %17, %18, %19, %20, %21, %22, %23, " \
        " %24, %25, %26, %27, %28, %29, %30, %31}, [%32];" \
        : "=r"((r)[0]),  "=r"((r)[1]),  "=r"((r)[2]),  "=r"((r)[3]), \
          "=r"((r)[4]),  "=r"((r)[5]),  "=r"((r)[6]),  "=r"((r)[7]), \
          "=r"((r)[8]),  "=r"((r)[9]),  "=r"((r)[10]), "=r"((r)[11]), \
          "=r"((r)[12]), "=r"((r)[13]), "=r"((r)[14]), "=r"((r)[15]), \
          "=r"((r)[16]), "=r"((r)[17]), "=r"((r)[18]), "=r"((r)[19]), \
          "=r"((r)[20]), "=r"((r)[21]), "=r"((r)[22]), "=r"((r)[23]), \
          "=r"((r)[24]), "=r"((r)[25]), "=r"((r)[26]), "=r"((r)[27]), \
          "=r"((r)[28]), "=r"((r)[29]), "=r"((r)[30]), "=r"((r)[31]) \
        : "r"(a))

__device__ __forceinline__ void mma_tf32(uint32_t tmem, uint64_t a, uint64_t b,
                                         uint32_t en) {
    asm volatile(
        "{\n\t.reg .pred p;\n\t"
        "setp.ne.u32 p, %4, 0;\n\t"
        "tcgen05.mma.cta_group::1.kind::tf32 [%0], %1, %2, %3, "
        "{%5, %5, %5, %5}, p;\n\t}"
        :: "r"(tmem), "l"(a), "l"(b), "r"(IDESC_TF32), "r"(en), "r"(0u)
        : "memory");
}
#endif

// ---------------------------------------------------------------------------
// One split-K unit: D[b=128][64 j] = A[128 x K] @ B[64 x K]^T in 3xTF32.
// R9-proven: LDG->split->STS staging, double-buffered K-chunks of 64,
// deferred per-buffer mbarrier waits.
__device__ __forceinline__ void run_unit(
    const float* __restrict__ Asrc, int lda,
    const float* __restrict__ Bsrc, int ldb,
    int K, uint32_t sb, float* __restrict__ smf, uint32_t tmem,
    float* __restrict__ dst, int ldd,
    int tid, uint32_t* committed, uint32_t* waited)
{
#if HAS_TCGEN05
    (void)smf;
    const int nc = K >> 6;
    for (int c = 0; c < nc; c++) {
        const int b = c & 1;
        const uint32_t mbar = sb + 8 + b * 8;
        if (committed[b] > waited[b]) {      // buffer still owned by MMA c-2
            mbar_wait(mbar, waited[b] & 1);
            waited[b]++;
        }
        const int c0 = c << 6;
        const uint32_t sA = sb + 1024 + b * 98304;
        const uint32_t sB = sA + 65536;

        // ---- A tile: 128 rows x 16 float4 (kch=64), split hi/lo ----
        for (int i = tid; i < 2048; i += 128) {
            int r = i >> 4, c4 = i & 15;
            float4 v = *reinterpret_cast<const float4*>(
                Asrc + (size_t)r * lda + c0 + c4 * 4);
            float4 hi, lo;
            split_f4(v, hi, lo);
            int bo = (((c4 >> 3) * 16 + (r >> 3)) << 10) | ((r & 7) << 7) | ((c4 & 7) << 4);
            uint32_t sw = bo ^ ((bo >> 3) & 0x70);
            asm volatile("st.shared.v4.b32 [%0], {%1,%2,%3,%4};"
                :: "r"(sA + sw), "r"(__float_as_uint(hi.x)),
                   "r"(__float_as_uint(hi.y)), "r"(__float_as_uint(hi.z)),
                   "r"(__float_as_uint(hi.w)) : "memory");
            asm volatile("st.shared.v4.b32 [%0], {%1,%2,%3,%4};"
                :: "r"(sA + 32768 + sw), "r"(__float_as_uint(lo.x)),
                   "r"(__float_as_uint(lo.y)), "r"(__float_as_uint(lo.z)),
                   "r"(__float_as_uint(lo.w)) : "memory");
        }
        // ---- B tile: 64 rows x 16 float4, split hi/lo ----
        for (int i = tid; i < 1024; i += 128) {
            int r = i >> 4, c4 = i & 15;
            float4 v = *reinterpret_cast<const float4*>(
                Bsrc + (size_t)r * ldb + c0 + c4 * 4);
            float4 hi, lo;
            split_f4(v, hi, lo);
            int bo = (((c4 >> 3) * 8 + (r >> 3)) << 10) | ((r & 7) << 7) | ((c4 & 7) << 4);
            uint32_t sw = bo ^ ((bo >> 3) & 0x70);
            asm volatile("st.shared.v4.b32 [%0], {%1,%2,%3,%4};"
                :: "r"(sB + sw), "r"(__float_as_uint(hi.x)),
                   "r"(__float_as_uint(hi.y)), "r"(__float_as_uint(hi.z)),
                   "r"(__float_as_uint(hi.w)) : "memory");
            asm volatile("st.shared.v4.b32 [%0], {%1,%2,%3,%4};"
                :: "r"(sB + 16384 + sw), "r"(__float_as_uint(lo.x)),
                   "r"(__float_as_uint(lo.y)), "r"(__float_as_uint(lo.z)),
                   "r"(__float_as_uint(lo.w)) : "memory");
        }
        asm volatile("fence.proxy.async.shared::cta;" ::: "memory");
        __syncthreads();

        if (tid < 32 && elect1()) {
            uint64_t dahi = sdesc(sA), dalo = sdesc(sA + 32768);
            uint64_t dbhi = sdesc(sB), dblo = sdesc(sB + 16384);
            #pragma unroll
            for (int s = 0; s < 8; s++) {    // kch=64 -> 8 steps of K=8
                uint64_t oa = (uint64_t)(((s >> 2) << 10) + ((s & 3) << 1));
                uint64_t ob = (uint64_t)(((s >> 2) << 9) + ((s & 3) << 1));
                mma_tf32(tmem, dahi + oa, dbhi + ob, (c > 0 || s > 0) ? 1u : 0u);
                mma_tf32(tmem, dahi + oa, dblo + ob, 1u);
                mma_tf32(tmem, dalo + oa, dbhi + ob, 1u);
            }
            asm volatile(
                "tcgen05.commit.cta_group::1.mbarrier::arrive::one.shared::cluster.b64 [%0];"
                :: "r"(mbar) : "memory");
        }
        committed[b]++;
    }
    // drain: all MMAs complete before LDTM
    #pragma unroll
    for (int b = 0; b < 2; b++) {
        if (committed[b] > waited[b]) {
            mbar_wait(sb + 8 + b * 8, waited[b] & 1);
            waited[b]++;
        }
    }
    asm volatile("tcgen05.fence::after_thread_sync;" ::: "memory");

    uint32_t d0[32], d1[32];
    LDTM32(d0, tmem);
    LDTM32(d1, tmem + 32);
    asm volatile("tcgen05.wait::ld.sync.aligned;" ::: "memory");
    asm volatile("tcgen05.fence::before_thread_sync;" ::: "memory");

    float* drow = dst + (size_t)tid * ldd;       // row b == tid
    #pragma unroll
    for (int c4 = 0; c4 < 8; c4++) {
        *reinterpret_cast<float4*>(drow + c4 * 4) = make_float4(
            __uint_as_float(d0[c4 * 4 + 0]), __uint_as_float(d0[c4 * 4 + 1]),
            __uint_as_float(d0[c4 * 4 + 2]), __uint_as_float(d0[c4 * 4 + 3]));
        *reinterpret_cast<float4*>(drow + 32 + c4 * 4) = make_float4(
            __uint_as_float(d1[c4 * 4 + 0]), __uint_as_float(d1[c4 * 4 + 1]),
            __uint_as_float(d1[c4 * 4 + 2]), __uint_as_float(d1[c4 * 4 + 3]));
    }
    __syncthreads();
#else
    // ---------------- SIMT fallback (base-arch pass only; never selected) --
    (void)sb; (void)tmem; (void)committed; (void)waited;
    float acc[64];
    #pragma unroll
    for (int j = 0; j < 64; j++) acc[j] = 0.f;
    for (int c0 = 0; c0 < K; c0 += 64) {
        for (int i = tid; i < 1024; i += 128) {
            int r = i >> 4, c4 = i & 15;
            *reinterpret_cast<float4*>(smf + r * 64 + c4 * 4) =
                *reinterpret_cast<const float4*>(Bsrc + (size_t)r * ldb + c0 + c4 * 4);
        }
        __syncthreads();
        const float* arow = Asrc + (size_t)tid * lda + c0;
        for (int k = 0; k < 64; k++) {
            float a = arow[k];
            #pragma unroll
            for (int j = 0; j < 64; j++) acc[j] += a * smf[j * 64 + k];
        }
        __syncthreads();
    }
    float* drow = dst + (size_t)tid * ldd;
    #pragma unroll
    for (int j = 0; j < 64; j += 4)
        *reinterpret_cast<float4*>(drow + j) =
            make_float4(acc[j], acc[j + 1], acc[j + 2], acc[j + 3]);
    __syncthreads();
#endif
}

// ---------------------------------------------------------------------------
// reduce C for timestep t: u = sigmoid(sum partC + bg); out = tanh+tanh
__device__ __forceinline__ void reduceC(
    int t, int u, int tid,
    const float* __restrict__ bg, const float* __restrict__ bo1,
    const float* __restrict__ bo2, float* __restrict__ out)
{
    const int n4 = BB * HH / 4;
    for (int i4 = u * 128 + tid; i4 < n4; i4 += NCTA * 128) {
        int j0 = (i4 << 2) & (HH - 1);
        float4 s = *reinterpret_cast<const float4*>(bg + j0);
        #pragma unroll
        for (int ss = 0; ss < 8; ss++) {
            float4 p = reinterpret_cast<const float4*>(partC)[ss * n4 + i4];
            s.x += p.x; s.y += p.y; s.z += p.z; s.w += p.w;
        }
        float4 r;
        r.x = 1.f / (1.f + expf(-s.x));
        r.y = 1.f / (1.f + expf(-s.y));
        r.z = 1.f / (1.f + expf(-s.z));
        r.w = 1.f / (1.f + expf(-s.w));
        reinterpret_cast<float4*>(g_u)[i4] = r;
    }
    for (int i = u * 128 + tid; i < BB * OO; i += NCTA * 128) {
        int b = i >> 6, o = i & 63;
        float s1 = bo1[o], s2 = bo2[o];
        #pragma unroll
        for (int ss = 0; ss < 4; ss++) {
            s1 += partH[ss * (BB * 128) + b * 128 + o];
            s2 += partH[ss * (BB * 128) + b * 128 + o + 64];
        }
        out[((size_t)b * TT + t) * OO + o] = tanhf(s1) + tanhf(s2);
    }
}

// ---------------------------------------------------------------------------
__global__ void __launch_bounds__(128, 1) k_rnn(
    const float* __restrict__ Wih1, const float* __restrict__ bih1,
    const float* __restrict__ Whh1, const float* __restrict__ bhh1,
    const float* __restrict__ Wih2, const float* __restrict__ bih2,
    const float* __restrict__ Whh2, const float* __restrict__ bhh2,
    const float* __restrict__ Wg,   const float* __restrict__ bg,
    const float* __restrict__ Wo1,  const float* __restrict__ bo1,
    const float* __restrict__ Wo2,  const float* __restrict__ bo2,
    float* __restrict__ out)
{
    extern __shared__ char dynsm[];
    const uint32_t sb = cvta_s(dynsm);
    float* smf = reinterpret_cast<float*>(dynsm);
    const int tid = threadIdx.x;
    const int u = blockIdx.x;
    unsigned epoch = 0;
    uint32_t committed[2] = {0u, 0u}, waited[2] = {0u, 0u};
    uint32_t tmem = 0;

#if HAS_TCGEN05
    if (tid < 32) {
        asm volatile(
            "tcgen05.alloc.cta_group::1.sync.aligned.shared::cta.b32 [%0], %1;"
            :: "r"(sb), "r"(64u) : "memory");
        asm volatile("tcgen05.relinquish_alloc_permit.cta_group::1.sync.aligned;");
    }
    if (tid == 0) {
        asm volatile("mbarrier.init.shared.b64 [%0], 1;" :: "r"(sb + 8) : "memory");
        asm volatile("mbarrier.init.shared.b64 [%0], 1;" :: "r"(sb + 16) : "memory");
    }
    __syncthreads();
    asm volatile("ld.shared.b32 %0, [%1];" : "=r"(tmem) : "r"(sb));
#endif

    const int n4 = BB * HH / 4;   // 32768 float4

    for (int t = 0; t < TT; t++) {
        // ========== merged phase: reduce C(t-1)  +  GEMM A(t) =============
        if (t > 0) reduceC(t - 1, u, tid, bg, bo1, bo2, out);
        if (u < 144) {
            int jt = u / 9, s = u - jt * 9;
            int j0 = jt * 64;
            float* dst = partA + (size_t)s * (BB * HH) + j0;
            if (s == 0)
                run_unit(bufX + (size_t)t * BB * II, II,
                         Wih1 + (size_t)j0 * II, II,
                         64, sb, smf, tmem, dst, HH, tid, committed, waited);
            else
                run_unit(bufH1 + (s - 1) * 128, HH,
                         Whh1 + (size_t)j0 * HH + (s - 1) * 128, HH,
                         128, sb, smf, tmem, dst, HH, tid, committed, waited);
        }
        gsync(epoch, u, tid);
        // ---- reduce A: h1 = tanh(sum9 + biases) ----
        for (int i4 = u * 128 + tid; i4 < n4; i4 += NCTA * 128) {
            int j0 = (i4 << 2) & (HH - 1);
            float4 b1 = *reinterpret_cast<const float4*>(bih1 + j0);
            float4 b2 = *reinterpret_cast<const float4*>(bhh1 + j0);
            float4 s = make_float4(b1.x + b2.x, b1.y + b2.y, b1.z + b2.z, b1.w + b2.w);
            #pragma unroll
            for (int ss = 0; ss < 9; ss++) {
                float4 p = reinterpret_cast<const float4*>(partA)[ss * n4 + i4];
                s.x += p.x; s.y += p.y; s.z += p.z; s.w += p.w;
            }
            reinterpret_cast<float4*>(bufH1)[i4] =
                make_float4(tanhf(s.x), tanhf(s.y), tanhf(s.z), tanhf(s.w));
        }
        gsync(epoch, u, tid);
        // ================= phase B: h2pre = h1@Wih2^T + h2@Whh2^T =========
        if (u < 128) {
            int jt = u >> 3, s = u & 7;
            int j0 = jt * 64;
            const float* A  = (s < 4) ? bufH1 + s * 256 : bufH2 + (s - 4) * 256;
            const float* Bw = (s < 4) ? Wih2 + (size_t)j0 * HH + s * 256
                                      : Whh2 + (size_t)j0 * HH + (s - 4) * 256;
            run_unit(A, HH, Bw, HH, 256, sb, smf, tmem,
                     partA + (size_t)s * (BB * HH) + j0, HH, tid,
                     committed, waited);
        }
        gsync(epoch, u, tid);
        // ---- reduce B: h2 = u*tanh(sum8+b) + (1-u)*h2 ----
        for (int i4 = u * 128 + tid; i4 < n4; i4 += NCTA * 128) {
            int j0 = (i4 << 2) & (HH - 1);
            float4 b1 = *reinterpret_cast<const float4*>(bih2 + j0);
            float4 b2 = *reinterpret_cast<const float4*>(bhh2 + j0);
            float4 s = make_float4(b1.x + b2.x, b1.y + b2.y, b1.z + b2.z, b1.w + b2.w);
            #pragma unroll
            for (int ss = 0; ss < 8; ss++) {
                float4 p = reinterpret_cast<const float4*>(partA)[ss * n4 + i4];
                s.x += p.x; s.y += p.y; s.z += p.z; s.w += p.w;
            }
            float4 uu = reinterpret_cast<const float4*>(g_u)[i4];
            float4 hp = reinterpret_cast<const float4*>(bufH2)[i4];
            float4 r;
            r.x = uu.x * tanhf(s.x) + (1.f - uu.x) * hp.x;
            r.y = uu.y * tanhf(s.y) + (1.f - uu.y) * hp.y;
            r.z = uu.z * tanhf(s.z) + (1.f - uu.z) * hp.z;
            r.w = uu.w * tanhf(s.w) + (1.f - uu.w) * hp.w;
            reinterpret_cast<float4*>(bufH2)[i4] = r;
        }
        gsync(epoch, u, tid);
        // ====== phase C: gate (128 units -> partC) + heads (8 -> partH) ===
        if (u < 128) {
            int jt = u >> 3, s = u & 7;
            int j0 = jt * 64;
            const float* A = (s < 4) ? bufH1 + s * 256 : bufH2 + (s - 4) * 256;
            run_unit(A, HH, Wg + (size_t)j0 * 2048 + s * 256, 2048,
                     256, sb, smf, tmem,
                     partC + (size_t)s * (BB * HH) + j0, HH, tid,
                     committed, waited);
        } else if (u < 136) {
            int i = u - 128;
            int head = i >> 2, s = i & 3;
            const float* A  = (head ? bufH2 : bufH1) + s * 256;
            const float* Bw = (head ? Wo2 : Wo1) + s * 256;
            run_unit(A, HH, Bw, HH, 256, sb, smf, tmem,
                     partH + (size_t)s * (BB * 128) + head * 64, 128, tid,
                     committed, waited);
        }
        gsync(epoch, u, tid);
    }
    // final epilogue: reduce C for t = TT-1
    reduceC(TT - 1, u, tid, bg, bo1, bo2, out);

    __syncthreads();
#if HAS_TCGEN05
    if (tid < 32) {
        asm volatile("tcgen05.dealloc.cta_group::1.sync.aligned.b32 %0, %1;"
                     :: "r"(tmem), "r"(64u));
    }
#endif
}

// ---------------------------------------------------------------------------
extern "C" void kernel_launch(void* const* d_in, const int* in_sizes, int n_in,
                              void* d_out, int out_size) {
    const float* x    = (const float*)d_in[0];
    const float* Wih1 = (const float*)d_in[1];
    const float* bih1 = (const float*)d_in[2];
    const float* Whh1 = (const float*)d_in[3];
    const float* bhh1 = (const float*)d_in[4];
    const float* Wih2 = (const float*)d_in[5];
    const float* bih2 = (const float*)d_in[6];
    const float* Whh2 = (const float*)d_in[7];
    const float* bhh2 = (const float*)d_in[8];
    const float* Wg   = (const float*)d_in[9];
    const float* bg   = (const float*)d_in[10];
    const float* Wo1  = (const float*)d_in[11];
    const float* bo1  = (const float*)d_in[12];
    const float* Wo2  = (const float*)d_in[13];
    const float* bo2  = (const float*)d_in[14];
    float* out = (float*)d_out;

    cudaFuncSetAttribute(k_rnn, cudaFuncAttributeMaxDynamicSharedMemorySize,
                         SMEM_BYTES);

    k_init<<<(BB * HH + 255) / 256, 256>>>();
    k_prepx<<<(TT * BB * II + 255) / 256, 256>>>(x);
    k_rnn<<<NCTA, 128, SMEM_BYTES>>>(Wih1, bih1, Whh1, bhh1,
                                     Wih2, bih2, Whh2, bhh2,
                                     Wg, bg, Wo1, bo1, Wo2, bo2, out);
}

// round 11
// speedup vs baseline: 1.0507x; 1.0507x over previous
#include <cuda_runtime.h>
#include <cstdint>

#define BB 128
#define TT 256
#define II 64
#define HH 1024
#define OO 64
#define NCTA 148

#if defined(__CUDA_ARCH_FEAT_SM103_ALL) || defined(__CUDA_ARCH_SPECIFIC__)
#define HAS_TCGEN05 1
#else
#define HAS_TCGEN05 0
#endif

// idesc: dtype=F32(1<<4), atype=TF32(2<<7), btype=TF32(2<<10), N/8=8<<17, M/16=8<<24
#define IDESC_TF32 0x8100910u

// smem: [0]=tmem ptr, [8]=mbar0, [16]=mbar1
// buffer b at 1024 + b*98304: Ahi +0, Alo +32768, Bhi +65536, Blo +81920
#define SMEM_BYTES 197632

// ---------------- persistent device globals (zero-initialized) -------------
__device__ float bufH1[BB * HH];       // h1 [b][j]
__device__ float bufH2[BB * HH];       // h2 [b][j]
__device__ float g_u[BB * HH];         // gate [b][j]
__device__ float pH1[3 * BB * HH];     // h1pre slices
__device__ float pH2[7 * BB * HH];     // h2pre slices (0-2: Whh2*h2, 3-6: Wih2*h1)
__device__ float pG [7 * BB * HH];     // gate slices  (0-2: Wg2*h2,  3-6: Wg1*h1)
__device__ float pO [7 * BB * OO];     // out slices   (0-2: Wo2*h2,  3-6: Wo1*h1)
__device__ volatile unsigned g_flags[NCTA * 32];  // barrier flags (128B stride)
__device__ unsigned g_epoch_base;                 // persists across launches

// ---------------------------------------------------------------------------
__device__ __forceinline__ uint32_t cvta_s(const void* p) {
    uint32_t a;
    asm("{ .reg .u64 t; cvta.to.shared.u64 t, %1; cvt.u32.u64 %0, t; }"
        : "=r"(a) : "l"(p));
    return a;
}

__device__ __forceinline__ bool elect1() {
    uint32_t p;
    asm volatile("{ .reg .pred p; elect.sync _|p, 0xFFFFFFFF; selp.b32 %0, 1, 0, p; }"
                 : "=r"(p));
    return p != 0;
}

__device__ __forceinline__ uint64_t sdesc(uint32_t addr) {
    // SW128 (2<<61) | version(1<<46) | SBO=64<<32 | LBO=1<<16
    return 0x4000404000010000ull | ((uint64_t)(addr >> 4) & 0x3FFF);
}

__device__ __forceinline__ void mbar_wait(uint32_t mbar, uint32_t parity) {
    asm volatile(
        "{\n\t.reg .pred P;\n\t"
        "WL%=:\n\t"
        "mbarrier.try_wait.parity.acquire.cta.shared::cta.b64 P, [%0], %1, 0x989680;\n\t"
        "@!P bra WL%=;\n\t}"
        :: "r"(mbar), "r"(parity) : "memory");
}

// Distributed-flag grid barrier (epochs continue across launches).
__device__ __forceinline__ void gsync(unsigned &epoch, int u, int tid) {
    __syncthreads();
    epoch++;
    __threadfence();
    if (tid == 0) g_flags[u * 32] = epoch;
    for (int i = tid; i < NCTA; i += 128)
        while (g_flags[i * 32] < epoch) { }
    __syncthreads();
    __threadfence();
}

// exact hi/lo split: hi = tf32 truncation (exact), lo = x - hi (exact)
__device__ __forceinline__ void split_f4(float4 v, float4 &hi, float4 &lo) {
    hi.x = __uint_as_float(__float_as_uint(v.x) & 0xFFFFE000u); lo.x = v.x - hi.x;
    hi.y = __uint_as_float(__float_as_uint(v.y) & 0xFFFFE000u); lo.y = v.y - hi.y;
    hi.z = __uint_as_float(__float_as_uint(v.z) & 0xFFFFE000u); lo.z = v.z - hi.z;
    hi.w = __uint_as_float(__float_as_uint(v.w) & 0xFFFFE000u); lo.w = v.w - hi.w;
}

#if HAS_TCGEN05
#define LDTM32(r, a) \
    asm volatile( \
        "tcgen05.ld.sync.aligned.32x32b.x32.b32 " \
        "{%0, %1, %2, %3, %4, %5, %6, %7, " \
        " %8, %9, %10, %11, %12, %13, %14, %15, " \
        " %16, %17, %18, %19, %20, %21, %22, %23, " \
        " %24, %25, %26, %27, %28, %29, %30, %31}, [%32];" \
        : "=r"((r)[0]),  "=r"((r)[1]),  "=r"((r)[2]),  "=r"((r)[3]), \
          "=r"((r)[4]),  "=r"((r)[5]),  "=r"((r)[6]),  "=r"((r)[7]), \
          "=r"((r)[8]),  "=r"((r)[9]),  "=r"((r)[10]), "=r"((r)[11]), \
          "=r"((r)[12]), "=r"((r)[13]), "=r"((r)[14]), "=r"((r)[15]), \
          "=r"((r)[16]), "=r"((r)[17]), "=r"((r)[18]), "=r"((r)[19]), \
          "=r"((r)[20]), "=r"((r)[21]), "=r"((r)[22]), "=r"((r)[23]), \
          "=r"((r)[24]), "=r"((r)[25]), "=r"((r)[26]), "=r"((r)[27]), \
          "=r"((r)[28]), "=r"((r)[29]), "=r"((r)[30]), "=r"((r)[31]) \
        : "r"(a))

__device__ __forceinline__ void mma_tf32(uint32_t tmem, uint64_t a, uint64_t b,
                                         uint32_t en) {
    asm volatile(
        "{\n\t.reg .pred p;\n\t"
        "setp.ne.u32 p, %4, 0;\n\t"
        "tcgen05.mma.cta_group::1.kind::tf32 [%0], %1, %2, %3, "
        "{%5, %5, %5, %5}, p;\n\t}"
        :: "r"(tmem), "l"(a), "l"(b), "r"(IDESC_TF32), "r"(en), "r"(0u)
        : "memory");
}
#endif

// ---------------------------------------------------------------------------
// One split-K unit: D[b=128][64 j] += A[128 x 64k-chunks] @ B[64 x ...]^T
// in 3xTF32 over absolute chunk range [c0,c1). Chunks with index < splitc
// come from (A0,lda0)/(B0,ldb0), the rest from (A1,lda1)/(B1,ldb1).
// R9-proven: LDG->split->STS staging, double-buffered chunks, deferred waits.
__device__ __forceinline__ void run_unit(
    int c0, int c1, int splitc,
    const float* __restrict__ A0, int lda0,
    const float* __restrict__ A1, int lda1,
    const float* __restrict__ B0, int ldb0,
    const float* __restrict__ B1, int ldb1,
    uint32_t sb, float* __restrict__ smf, uint32_t tmem,
    float* __restrict__ dst, int ldd,
    int tid, uint32_t* committed, uint32_t* waited)
{
#if HAS_TCGEN05
    (void)smf;
    for (int c = c0; c < c1; c++) {
        const int b = (c - c0) & 1;
        const uint32_t mbar = sb + 8 + b * 8;
        if (committed[b] > waited[b]) {
            mbar_wait(mbar, waited[b] & 1);
            waited[b]++;
        }
        const float* Ap; int la;
        const float* Bp; int lb;
        if (c < splitc) { Ap = A0 + c * 64;            la = lda0;
                          Bp = B0 + c * 64;            lb = ldb0; }
        else            { Ap = A1 + (c - splitc) * 64; la = lda1;
                          Bp = B1 + (c - splitc) * 64; lb = ldb1; }
        const uint32_t sA = sb + 1024 + b * 98304;
        const uint32_t sB = sA + 65536;

        // A tile: 128 rows x 16 float4, split hi/lo
        for (int i = tid; i < 2048; i += 128) {
            int r = i >> 4, c4 = i & 15;
            float4 v = *reinterpret_cast<const float4*>(Ap + (size_t)r * la + c4 * 4);
            float4 hi, lo;
            split_f4(v, hi, lo);
            int bo = (((c4 >> 3) * 16 + (r >> 3)) << 10) | ((r & 7) << 7) | ((c4 & 7) << 4);
            uint32_t sw = bo ^ ((bo >> 3) & 0x70);
            asm volatile("st.shared.v4.b32 [%0], {%1,%2,%3,%4};"
                :: "r"(sA + sw), "r"(__float_as_uint(hi.x)),
                   "r"(__float_as_uint(hi.y)), "r"(__float_as_uint(hi.z)),
                   "r"(__float_as_uint(hi.w)) : "memory");
            asm volatile("st.shared.v4.b32 [%0], {%1,%2,%3,%4};"
                :: "r"(sA + 32768 + sw), "r"(__float_as_uint(lo.x)),
                   "r"(__float_as_uint(lo.y)), "r"(__float_as_uint(lo.z)),
                   "r"(__float_as_uint(lo.w)) : "memory");
        }
        // B tile: 64 rows x 16 float4, split hi/lo
        for (int i = tid; i < 1024; i += 128) {
            int r = i >> 4, c4 = i & 15;
            float4 v = *reinterpret_cast<const float4*>(Bp + (size_t)r * lb + c4 * 4);
            float4 hi, lo;
            split_f4(v, hi, lo);
            int bo = (((c4 >> 3) * 8 + (r >> 3)) << 10) | ((r & 7) << 7) | ((c4 & 7) << 4);
            uint32_t sw = bo ^ ((bo >> 3) & 0x70);
            asm volatile("st.shared.v4.b32 [%0], {%1,%2,%3,%4};"
                :: "r"(sB + sw), "r"(__float_as_uint(hi.x)),
                   "r"(__float_as_uint(hi.y)), "r"(__float_as_uint(hi.z)),
                   "r"(__float_as_uint(hi.w)) : "memory");
            asm volatile("st.shared.v4.b32 [%0], {%1,%2,%3,%4};"
                :: "r"(sB + 16384 + sw), "r"(__float_as_uint(lo.x)),
                   "r"(__float_as_uint(lo.y)), "r"(__float_as_uint(lo.z)),
                   "r"(__float_as_uint(lo.w)) : "memory");
        }
        asm volatile("fence.proxy.async.shared::cta;" ::: "memory");
        __syncthreads();

        if (tid < 32 && elect1()) {
            uint64_t dahi = sdesc(sA), dalo = sdesc(sA + 32768);
            uint64_t dbhi = sdesc(sB), dblo = sdesc(sB + 16384);
            #pragma unroll
            for (int s = 0; s < 8; s++) {
                uint64_t oa = (uint64_t)(((s >> 2) << 10) + ((s & 3) << 1));
                uint64_t ob = (uint64_t)(((s >> 2) << 9) + ((s & 3) << 1));
                mma_tf32(tmem, dahi + oa, dbhi + ob, (c > c0 || s > 0) ? 1u : 0u);
                mma_tf32(tmem, dahi + oa, dblo + ob, 1u);
                mma_tf32(tmem, dalo + oa, dbhi + ob, 1u);
            }
            asm volatile(
                "tcgen05.commit.cta_group::1.mbarrier::arrive::one.shared::cluster.b64 [%0];"
                :: "r"(mbar) : "memory");
        }
        committed[b]++;
    }
    #pragma unroll
    for (int b = 0; b < 2; b++) {
        if (committed[b] > waited[b]) {
            mbar_wait(sb + 8 + b * 8, waited[b] & 1);
            waited[b]++;
        }
    }
    asm volatile("tcgen05.fence::after_thread_sync;" ::: "memory");

    uint32_t d0[32], d1[32];
    LDTM32(d0, tmem);
    LDTM32(d1, tmem + 32);
    asm volatile("tcgen05.wait::ld.sync.aligned;" ::: "memory");
    asm volatile("tcgen05.fence::before_thread_sync;" ::: "memory");

    float* drow = dst + (size_t)tid * ldd;       // row b == tid
    #pragma unroll
    for (int c4 = 0; c4 < 8; c4++) {
        *reinterpret_cast<float4*>(drow + c4 * 4) = make_float4(
            __uint_as_float(d0[c4 * 4 + 0]), __uint_as_float(d0[c4 * 4 + 1]),
            __uint_as_float(d0[c4 * 4 + 2]), __uint_as_float(d0[c4 * 4 + 3]));
        *reinterpret_cast<float4*>(drow + 32 + c4 * 4) = make_float4(
            __uint_as_float(d1[c4 * 4 + 0]), __uint_as_float(d1[c4 * 4 + 1]),
            __uint_as_float(d1[c4 * 4 + 2]), __uint_as_float(d1[c4 * 4 + 3]));
    }
    __syncthreads();
#else
    // ---------------- SIMT fallback (base-arch pass only; never selected) --
    (void)sb; (void)tmem; (void)committed; (void)waited;
    float acc[64];
    #pragma unroll
    for (int j = 0; j < 64; j++) acc[j] = 0.f;
    for (int c = c0; c < c1; c++) {
        const float* Ap; int la;
        const float* Bp; int lb;
        if (c < splitc) { Ap = A0 + c * 64;            la = lda0;
                          Bp = B0 + c * 64;            lb = ldb0; }
        else            { Ap = A1 + (c - splitc) * 64; la = lda1;
                          Bp = B1 + (c - splitc) * 64; lb = ldb1; }
        for (int i = tid; i < 1024; i += 128) {
            int r = i >> 4, c4 = i & 15;
            *reinterpret_cast<float4*>(smf + r * 64 + c4 * 4) =
                *reinterpret_cast<const float4*>(Bp + (size_t)r * lb + c4 * 4);
        }
        __syncthreads();
        const float* arow = Ap + (size_t)tid * la;
        for (int k = 0; k < 64; k++) {
            float a = arow[k];
            #pragma unroll
            for (int j = 0; j < 64; j++) acc[j] += a * smf[j * 64 + k];
        }
        __syncthreads();
    }
    float* drow = dst + (size_t)tid * ldd;
    #pragma unroll
    for (int j = 0; j < 64; j += 4)
        *reinterpret_cast<float4*>(drow + j) =
            make_float4(acc[j], acc[j + 1], acc[j + 2], acc[j + 3]);
    __syncthreads();
#endif
}

// ---------------------------------------------------------------------------
__global__ void __launch_bounds__(128, 1) k_rnn(
    const float* __restrict__ x,
    const float* __restrict__ Wih1, const float* __restrict__ bih1,
    const float* __restrict__ Whh1, const float* __restrict__ bhh1,
    const float* __restrict__ Wih2, const float* __restrict__ bih2,
    const float* __restrict__ Whh2, const float* __restrict__ bhh2,
    const float* __restrict__ Wg,   const float* __restrict__ bg,
    const float* __restrict__ Wo1,  const float* __restrict__ bo1,
    const float* __restrict__ Wo2,  const float* __restrict__ bo2,
    float* __restrict__ out)
{
    extern __shared__ char dynsm[];
    const uint32_t sb = cvta_s(dynsm);
    float* smf = reinterpret_cast<float*>(dynsm);
    const int tid = threadIdx.x;
    const int u = blockIdx.x;
    unsigned epoch = g_epoch_base;           // continue across launches
    uint32_t committed[2] = {0u, 0u}, waited[2] = {0u, 0u};
    uint32_t tmem = 0;

#if HAS_TCGEN05
    if (tid < 32) {
        asm volatile(
            "tcgen05.alloc.cta_group::1.sync.aligned.shared::cta.b32 [%0], %1;"
            :: "r"(sb), "r"(64u) : "memory");
        asm volatile("tcgen05.relinquish_alloc_permit.cta_group::1.sync.aligned;");
    }
    if (tid == 0) {
        asm volatile("mbarrier.init.shared.b64 [%0], 1;" :: "r"(sb + 8) : "memory");
        asm volatile("mbarrier.init.shared.b64 [%0], 1;" :: "r"(sb + 16) : "memory");
    }
    __syncthreads();
    asm volatile("ld.shared.b32 %0, [%1];" : "=r"(tmem) : "r"(sb));
#endif

    const int n4 = BB * HH / 4;   // 32768 float4

    // ---- state init (re-done each launch; replay-safe) ----
    for (int i = u * 128 + tid; i < BB * HH; i += NCTA * 128) {
        bufH1[i] = 0.f; bufH2[i] = 0.f; g_u[i] = 1.f;
    }
    gsync(epoch, u, tid);

    for (int t = 0; t <= TT; t++) {
        // ===== phase 1: all GEMMs depending on h1(t-1), h2(t-1), x(t) =====
        if (u < 48 && t < TT) {
            // T1: h1pre = x(t)@Wih1^T + h1@Whh1^T  (17 chunks, 3 slices)
            int jt = u / 3, s = u % 3;
            int c0 = (s == 0) ? 0 : (s == 1 ? 6 : 12);
            int c1 = (s == 0) ? 6 : (s == 1 ? 12 : 17);
            run_unit(c0, c1, 1,
                     x + (size_t)t * 64, TT * II, bufH1, HH,
                     Wih1 + (size_t)jt * 64 * II, II,
                     Whh1 + (size_t)jt * 64 * HH, HH,
                     sb, smf, tmem,
                     pH1 + (size_t)s * BB * HH + jt * 64, HH,
                     tid, committed, waited);
        } else if (u < 96 && t < TT) {
            // T2: h2@Wg2^T (gate, second half of Wg)  (16 chunks, 3 slices)
            int idx = u - 48, jt = idx / 3, s = idx % 3;
            int c0 = (s == 0) ? 0 : (s == 1 ? 6 : 11);
            int c1 = (s == 0) ? 6 : (s == 1 ? 11 : 16);
            run_unit(c0, c1, 0, nullptr, 0, bufH2, HH, nullptr, 0,
                     Wg + (size_t)jt * 64 * 2048 + 1024, 2048,
                     sb, smf, tmem,
                     pG + (size_t)s * BB * HH + jt * 64, HH,
                     tid, committed, waited);
        } else if (u < 144 && t < TT) {
            // T3: h2@Whh2^T  (16 chunks, 3 slices)
            int idx = u - 96, jt = idx / 3, s = idx % 3;
            int c0 = (s == 0) ? 0 : (s == 1 ? 6 : 11);
            int c1 = (s == 0) ? 6 : (s == 1 ? 11 : 16);
            run_unit(c0, c1, 0, nullptr, 0, bufH2, HH, nullptr, 0,
                     Whh2 + (size_t)jt * 64 * HH, HH,
                     sb, smf, tmem,
                     pH2 + (size_t)s * BB * HH + jt * 64, HH,
                     tid, committed, waited);
        } else if (u >= 144 && u < 147) {
            // T4: h2@Wo2^T  (runs at every t incl. t==TT for out(TT-1))
            int s = u - 144;
            int c0 = (s == 0) ? 0 : (s == 1 ? 6 : 11);
            int c1 = (s == 0) ? 6 : (s == 1 ? 11 : 16);
            run_unit(c0, c1, 0, nullptr, 0, bufH2, HH, nullptr, 0,
                     Wo2, HH,
                     sb, smf, tmem,
                     pO + (size_t)s * BB * OO, OO,
                     tid, committed, waited);
        }
        gsync(epoch, u, tid);

        // ===== reduce 1: h1(t); u(t-1); out(t-1) =====
        if (t < TT) {
            for (int i4 = u * 128 + tid; i4 < n4; i4 += NCTA * 128) {
                int j0 = (i4 << 2) & (HH - 1);
                float4 b1 = *reinterpret_cast<const float4*>(bih1 + j0);
                float4 b2 = *reinterpret_cast<const float4*>(bhh1 + j0);
                float4 s = make_float4(b1.x + b2.x, b1.y + b2.y,
                                       b1.z + b2.z, b1.w + b2.w);
                #pragma unroll
                for (int ss = 0; ss < 3; ss++) {
                    float4 p = reinterpret_cast<const float4*>(pH1)[ss * n4 + i4];
                    s.x += p.x; s.y += p.y; s.z += p.z; s.w += p.w;
                }
                reinterpret_cast<float4*>(bufH1)[i4] =
                    make_float4(tanhf(s.x), tanhf(s.y), tanhf(s.z), tanhf(s.w));
            }
        }
        if (t > 0 && t < TT) {
            for (int i4 = u * 128 + tid; i4 < n4; i4 += NCTA * 128) {
                int j0 = (i4 << 2) & (HH - 1);
                float4 s = *reinterpret_cast<const float4*>(bg + j0);
                #pragma unroll
                for (int ss = 0; ss < 7; ss++) {
                    float4 p = reinterpret_cast<const float4*>(pG)[ss * n4 + i4];
                    s.x += p.x; s.y += p.y; s.z += p.z; s.w += p.w;
                }
                float4 r;
                r.x = 1.f / (1.f + expf(-s.x));
                r.y = 1.f / (1.f + expf(-s.y));
                r.z = 1.f / (1.f + expf(-s.z));
                r.w = 1.f / (1.f + expf(-s.w));
                reinterpret_cast<float4*>(g_u)[i4] = r;
            }
        }
        if (t > 0) {
            for (int i4 = u * 128 + tid; i4 < BB * OO / 4; i4 += NCTA * 128) {
                int b = i4 >> 4;
                int o4 = (i4 & 15) * 4;
                float4 s1 = *reinterpret_cast<const float4*>(bo1 + o4);
                float4 s2 = *reinterpret_cast<const float4*>(bo2 + o4);
                #pragma unroll
                for (int ss = 3; ss < 7; ss++) {
                    float4 p = *reinterpret_cast<const float4*>(
                        pO + (size_t)ss * BB * OO + b * OO + o4);
                    s1.x += p.x; s1.y += p.y; s1.z += p.z; s1.w += p.w;
                }
                #pragma unroll
                for (int ss = 0; ss < 3; ss++) {
                    float4 p = *reinterpret_cast<const float4*>(
                        pO + (size_t)ss * BB * OO + b * OO + o4);
                    s2.x += p.x; s2.y += p.y; s2.z += p.z; s2.w += p.w;
                }
                float4 r;
                r.x = tanhf(s1.x) + tanhf(s2.x);
                r.y = tanhf(s1.y) + tanhf(s2.y);
                r.z = tanhf(s1.z) + tanhf(s2.z);
                r.w = tanhf(s1.w) + tanhf(s2.w);
                *reinterpret_cast<float4*>(
                    out + (size_t)b * TT * OO + (t - 1) * OO + o4) = r;
            }
        }
        if (t == TT) break;
        gsync(epoch, u, tid);

        // ===== phase 2: all GEMMs depending on h1(t) =====
        if (u < 64) {
            // T5: h1@Wih2^T  (16 chunks, 4 slices)
            int jt = u >> 2, s = u & 3;
            run_unit(s * 4, s * 4 + 4, 0, nullptr, 0, bufH1, HH, nullptr, 0,
                     Wih2 + (size_t)jt * 64 * HH, HH,
                     sb, smf, tmem,
                     pH2 + (size_t)(3 + s) * BB * HH + jt * 64, HH,
                     tid, committed, waited);
        } else if (u < 128) {
            // T6: h1@Wg1^T (first half of Wg)
            int idx = u - 64, jt = idx >> 2, s = idx & 3;
            run_unit(s * 4, s * 4 + 4, 0, nullptr, 0, bufH1, HH, nullptr, 0,
                     Wg + (size_t)jt * 64 * 2048, 2048,
                     sb, smf, tmem,
                     pG + (size_t)(3 + s) * BB * HH + jt * 64, HH,
                     tid, committed, waited);
        } else if (u < 132) {
            // T7: h1@Wo1^T
            int s = u - 128;
            run_unit(s * 4, s * 4 + 4, 0, nullptr, 0, bufH1, HH, nullptr, 0,
                     Wo1, HH,
                     sb, smf, tmem,
                     pO + (size_t)(3 + s) * BB * OO, OO,
                     tid, committed, waited);
        }
        gsync(epoch, u, tid);

        // ===== reduce 2: h2(t) = u(t-1)*tanh(.) + (1-u(t-1))*h2(t-1) =====
        for (int i4 = u * 128 + tid; i4 < n4; i4 += NCTA * 128) {
            int j0 = (i4 << 2) & (HH - 1);
            float4 b1 = *reinterpret_cast<const float4*>(bih2 + j0);
            float4 b2 = *reinterpret_cast<const float4*>(bhh2 + j0);
            float4 s = make_float4(b1.x + b2.x, b1.y + b2.y,
                                   b1.z + b2.z, b1.w + b2.w);
            #pragma unroll
            for (int ss = 0; ss < 7; ss++) {
                float4 p = reinterpret_cast<const float4*>(pH2)[ss * n4 + i4];
                s.x += p.x; s.y += p.y; s.z += p.z; s.w += p.w;
            }
            float4 uu = reinterpret_cast<const float4*>(g_u)[i4];
            float4 hp = reinterpret_cast<const float4*>(bufH2)[i4];
            float4 r;
            r.x = uu.x * tanhf(s.x) + (1.f - uu.x) * hp.x;
            r.y = uu.y * tanhf(s.y) + (1.f - uu.y) * hp.y;
            r.z = uu.z * tanhf(s.z) + (1.f - uu.z) * hp.z;
            r.w = uu.w * tanhf(s.w) + (1.f - uu.w) * hp.w;
            reinterpret_cast<float4*>(bufH2)[i4] = r;
        }
        gsync(epoch, u, tid);
    }

    // persist epoch for next launch (all CTAs computed the same count)
    if (u == 0 && tid == 0) g_epoch_base = epoch;

    __syncthreads();
#if HAS_TCGEN05
    if (tid < 32) {
        asm volatile("tcgen05.dealloc.cta_group::1.sync.aligned.b32 %0, %1;"
                     :: "r"(tmem), "r"(64u));
    }
#endif
}

// ---------------------------------------------------------------------------
extern "C" void kernel_launch(void* const* d_in, const int* in_sizes, int n_in,
                              void* d_out, int out_size) {
    const float* x    = (const float*)d_in[0];
    const float* Wih1 = (const float*)d_in[1];
    const float* bih1 = (const float*)d_in[2];
    const float* Whh1 = (const float*)d_in[3];
    const float* bhh1 = (const float*)d_in[4];
    const float* Wih2 = (const float*)d_in[5];
    const float* bih2 = (const float*)d_in[6];
    const float* Whh2 = (const float*)d_in[7];
    const float* bhh2 = (const float*)d_in[8];
    const float* Wg   = (const float*)d_in[9];
    const float* bg   = (const float*)d_in[10];
    const float* Wo1  = (const float*)d_in[11];
    const float* bo1  = (const float*)d_in[12];
    const float* Wo2  = (const float*)d_in[13];
    const float* bo2  = (const float*)d_in[14];
    float* out = (float*)d_out;

    cudaFuncSetAttribute(k_rnn, cudaFuncAttributeMaxDynamicSharedMemorySize,
                         SMEM_BYTES);

    k_rnn<<<NCTA, 128, SMEM_BYTES>>>(x, Wih1, bih1, Whh1, bhh1,
                                     Wih2, bih2, Whh2, bhh2,
                                     Wg, bg, Wo1, bo1, Wo2, bo2, out);
}

// round 12
// speedup vs baseline: 1.6874x; 1.6060x over previous
#include <cuda_runtime.h>
#include <cstdint>

#define BB 128
#define TT 256
#define II 64
#define HH 1024
#define OO 64
#define NCTA 148
#define NTH 256

#if defined(__CUDA_ARCH_FEAT_SM103_ALL) || defined(__CUDA_ARCH_SPECIFIC__)
#define HAS_TCGEN05 1
#else
#define HAS_TCGEN05 0
#endif

// idesc: dtype=F32(1<<4), atype=TF32(2<<7), btype=TF32(2<<10), N/8=8<<17, M/16=8<<24
#define IDESC_TF32 0x8100910u

// smem: [0]=tmem ptr, [8]=mbar0, [16]=mbar1
// buffer b at 1024 + b*98304: Ahi +0, Alo +32768, Bhi +65536, Blo +81920
#define SMEM_BYTES 197632

// ---------------- persistent device globals (zero-initialized) -------------
__device__ float bufH1[BB * HH];       // h1 [b][j]
__device__ float bufH2[BB * HH];       // h2 [b][j]
__device__ float g_u[BB * HH];         // gate [b][j]
__device__ float pH1[3 * BB * HH];     // h1pre slices
__device__ float pH2[7 * BB * HH];     // h2pre slices (0-2: Whh2*h2, 3-6: Wih2*h1)
__device__ float pG [7 * BB * HH];     // gate slices  (0-2: Wg2*h2,  3-6: Wg1*h1)
__device__ float pO [7 * BB * OO];     // out slices   (0-2: Wo2*h2,  3-6: Wo1*h1)
__device__ volatile unsigned g_flags[NCTA * 32];  // barrier flags (128B stride)
__device__ unsigned g_epoch_base;                 // persists across launches

// ---------------------------------------------------------------------------
__device__ __forceinline__ uint32_t cvta_s(const void* p) {
    uint32_t a;
    asm("{ .reg .u64 t; cvta.to.shared.u64 t, %1; cvt.u32.u64 %0, t; }"
        : "=r"(a) : "l"(p));
    return a;
}

__device__ __forceinline__ bool elect1() {
    uint32_t p;
    asm volatile("{ .reg .pred p; elect.sync _|p, 0xFFFFFFFF; selp.b32 %0, 1, 0, p; }"
                 : "=r"(p));
    return p != 0;
}

__device__ __forceinline__ uint64_t sdesc(uint32_t addr) {
    // SW128 (2<<61) | version(1<<46) | SBO=64<<32 | LBO=1<<16
    return 0x4000404000010000ull | ((uint64_t)(addr >> 4) & 0x3FFF);
}

__device__ __forceinline__ void mbar_wait(uint32_t mbar, uint32_t parity) {
    asm volatile(
        "{\n\t.reg .pred P;\n\t"
        "WL%=:\n\t"
        "mbarrier.try_wait.parity.acquire.cta.shared::cta.b64 P, [%0], %1, 0x989680;\n\t"
        "@!P bra WL%=;\n\t}"
        :: "r"(mbar), "r"(parity) : "memory");
}

// Distributed-flag grid barrier (epochs continue across launches).
__device__ __forceinline__ void gsync(unsigned &epoch, int u, int tid) {
    __syncthreads();
    epoch++;
    __threadfence();
    if (tid == 0) g_flags[u * 32] = epoch;
    for (int i = tid; i < NCTA; i += NTH)
        while (g_flags[i * 32] < epoch) { }
    __syncthreads();
    __threadfence();
}

// exact hi/lo split: hi = tf32 truncation (exact), lo = x - hi (exact)
__device__ __forceinline__ void split_f4(float4 v, float4 &hi, float4 &lo) {
    hi.x = __uint_as_float(__float_as_uint(v.x) & 0xFFFFE000u); lo.x = v.x - hi.x;
    hi.y = __uint_as_float(__float_as_uint(v.y) & 0xFFFFE000u); lo.y = v.y - hi.y;
    hi.z = __uint_as_float(__float_as_uint(v.z) & 0xFFFFE000u); lo.z = v.z - hi.z;
    hi.w = __uint_as_float(__float_as_uint(v.w) & 0xFFFFE000u); lo.w = v.w - hi.w;
}

#if HAS_TCGEN05
#define LDTM32(r, a) \
    asm volatile( \
        "tcgen05.ld.sync.aligned.32x32b.x32.b32 " \
        "{%0, %1, %2, %3, %4, %5, %6, %7, " \
        " %8, %9, %10, %11, %12, %13, %14, %15, " \
        " %16, %17, %18, %19, %20, %21, %22, %23, " \
        " %24, %25, %26, %27, %28, %29, %30, %31}, [%32];" \
        : "=r"((r)[0]),  "=r"((r)[1]),  "=r"((r)[2]),  "=r"((r)[3]), \
          "=r"((r)[4]),  "=r"((r)[5]),  "=r"((r)[6]),  "=r"((r)[7]), \
          "=r"((r)[8]),  "=r"((r)[9]),  "=r"((r)[10]), "=r"((r)[11]), \
          "=r"((r)[12]), "=r"((r)[13]), "=r"((r)[14]), "=r"((r)[15]), \
          "=r"((r)[16]), "=r"((r)[17]), "=r"((r)[18]), "=r"((r)[19]), \
          "=r"((r)[20]), "=r"((r)[21]), "=r"((r)[22]), "=r"((r)[23]), \
          "=r"((r)[24]), "=r"((r)[25]), "=r"((r)[26]), "=r"((r)[27]), \
          "=r"((r)[28]), "=r"((r)[29]), "=r"((r)[30]), "=r"((r)[31]) \
        : "r"(a))

__device__ __forceinline__ void mma_tf32(uint32_t tmem, uint64_t a, uint64_t b,
                                         uint32_t en) {
    asm volatile(
        "{\n\t.reg .pred p;\n\t"
        "setp.ne.u32 p, %4, 0;\n\t"
        "tcgen05.mma.cta_group::1.kind::tf32 [%0], %1, %2, %3, "
        "{%5, %5, %5, %5}, p;\n\t}"
        :: "r"(tmem), "l"(a), "l"(b), "r"(IDESC_TF32), "r"(en), "r"(0u)
        : "memory");
}
#endif

// ---------------------------------------------------------------------------
// One split-K unit: D[b=128][64 j] += A[128 x 64k-chunks] @ B[64 x ...]^T
// in 3xTF32 over absolute chunk range [c0,c1). Chunks with index < splitc
// come from (A0,lda0)/(B0,ldb0), the rest from (A1,lda1)/(B1,ldb1).
// Staging: batched LDG->regs (MLP 8/4), then split->STS. 256 threads.
__device__ __forceinline__ void run_unit(
    int c0, int c1, int splitc,
    const float* __restrict__ A0, int lda0,
    const float* __restrict__ A1, int lda1,
    const float* __restrict__ B0, int ldb0,
    const float* __restrict__ B1, int ldb1,
    uint32_t sb, float* __restrict__ smf, uint32_t tmem,
    float* __restrict__ dst, int ldd,
    int tid, uint32_t* committed, uint32_t* waited)
{
#if HAS_TCGEN05
    (void)smf;
    for (int c = c0; c < c1; c++) {
        const int b = (c - c0) & 1;
        const uint32_t mbar = sb + 8 + b * 8;
        if (committed[b] > waited[b]) {
            mbar_wait(mbar, waited[b] & 1);
            waited[b]++;
        }
        const float* Ap; int la;
        const float* Bp; int lb;
        if (c < splitc) { Ap = A0 + c * 64;            la = lda0;
                          Bp = B0 + c * 64;            lb = ldb0; }
        else            { Ap = A1 + (c - splitc) * 64; la = lda1;
                          Bp = B1 + (c - splitc) * 64; lb = ldb1; }
        const uint32_t sA = sb + 1024 + b * 98304;
        const uint32_t sB = sA + 65536;

        // ---- batched loads: all LDGs issued before any use (high MLP) ----
        float4 va[8], vb[4];
        #pragma unroll
        for (int r = 0; r < 8; r++) {               // A: 2048 float4 / 256
            int i = tid + r * NTH;
            int rr = i >> 4, c4 = i & 15;
            va[r] = *reinterpret_cast<const float4*>(Ap + (size_t)rr * la + c4 * 4);
        }
        #pragma unroll
        for (int r = 0; r < 4; r++) {               // B: 1024 float4 / 256
            int i = tid + r * NTH;
            int rr = i >> 4, c4 = i & 15;
            vb[r] = *reinterpret_cast<const float4*>(Bp + (size_t)rr * lb + c4 * 4);
        }
        // ---- split + STS ----
        #pragma unroll
        for (int r = 0; r < 8; r++) {
            int i = tid + r * NTH;
            int rr = i >> 4, c4 = i & 15;
            float4 hi, lo;
            split_f4(va[r], hi, lo);
            int bo = (((c4 >> 3) * 16 + (rr >> 3)) << 10) | ((rr & 7) << 7) | ((c4 & 7) << 4);
            uint32_t sw = bo ^ ((bo >> 3) & 0x70);
            asm volatile("st.shared.v4.b32 [%0], {%1,%2,%3,%4};"
                :: "r"(sA + sw), "r"(__float_as_uint(hi.x)),
                   "r"(__float_as_uint(hi.y)), "r"(__float_as_uint(hi.z)),
                   "r"(__float_as_uint(hi.w)) : "memory");
            asm volatile("st.shared.v4.b32 [%0], {%1,%2,%3,%4};"
                :: "r"(sA + 32768 + sw), "r"(__float_as_uint(lo.x)),
                   "r"(__float_as_uint(lo.y)), "r"(__float_as_uint(lo.z)),
                   "r"(__float_as_uint(lo.w)) : "memory");
        }
        #pragma unroll
        for (int r = 0; r < 4; r++) {
            int i = tid + r * NTH;
            int rr = i >> 4, c4 = i & 15;
            float4 hi, lo;
            split_f4(vb[r], hi, lo);
            int bo = (((c4 >> 3) * 8 + (rr >> 3)) << 10) | ((rr & 7) << 7) | ((c4 & 7) << 4);
            uint32_t sw = bo ^ ((bo >> 3) & 0x70);
            asm volatile("st.shared.v4.b32 [%0], {%1,%2,%3,%4};"
                :: "r"(sB + sw), "r"(__float_as_uint(hi.x)),
                   "r"(__float_as_uint(hi.y)), "r"(__float_as_uint(hi.z)),
                   "r"(__float_as_uint(hi.w)) : "memory");
            asm volatile("st.shared.v4.b32 [%0], {%1,%2,%3,%4};"
                :: "r"(sB + 16384 + sw), "r"(__float_as_uint(lo.x)),
                   "r"(__float_as_uint(lo.y)), "r"(__float_as_uint(lo.z)),
                   "r"(__float_as_uint(lo.w)) : "memory");
        }
        asm volatile("fence.proxy.async.shared::cta;" ::: "memory");
        __syncthreads();

        if (tid < 32 && elect1()) {
            uint64_t dahi = sdesc(sA), dalo = sdesc(sA + 32768);
            uint64_t dbhi = sdesc(sB), dblo = sdesc(sB + 16384);
            #pragma unroll
            for (int s = 0; s < 8; s++) {
                uint64_t oa = (uint64_t)(((s >> 2) << 10) + ((s & 3) << 1));
                uint64_t ob = (uint64_t)(((s >> 2) << 9) + ((s & 3) << 1));
                mma_tf32(tmem, dahi + oa, dbhi + ob, (c > c0 || s > 0) ? 1u : 0u);
                mma_tf32(tmem, dahi + oa, dblo + ob, 1u);
                mma_tf32(tmem, dalo + oa, dbhi + ob, 1u);
            }
            asm volatile(
                "tcgen05.commit.cta_group::1.mbarrier::arrive::one.shared::cluster.b64 [%0];"
                :: "r"(mbar) : "memory");
        }
        committed[b]++;
    }
    #pragma unroll
    for (int b = 0; b < 2; b++) {
        if (committed[b] > waited[b]) {
            mbar_wait(sb + 8 + b * 8, waited[b] & 1);
            waited[b]++;
        }
    }
    asm volatile("tcgen05.fence::after_thread_sync;" ::: "memory");

    if (tid < 128) {
        uint32_t d0[32], d1[32];
        LDTM32(d0, tmem);
        LDTM32(d1, tmem + 32);
        asm volatile("tcgen05.wait::ld.sync.aligned;" ::: "memory");
        asm volatile("tcgen05.fence::before_thread_sync;" ::: "memory");

        float* drow = dst + (size_t)tid * ldd;       // row b == tid
        #pragma unroll
        for (int c4 = 0; c4 < 8; c4++) {
            *reinterpret_cast<float4*>(drow + c4 * 4) = make_float4(
                __uint_as_float(d0[c4 * 4 + 0]), __uint_as_float(d0[c4 * 4 + 1]),
                __uint_as_float(d0[c4 * 4 + 2]), __uint_as_float(d0[c4 * 4 + 3]));
            *reinterpret_cast<float4*>(drow + 32 + c4 * 4) = make_float4(
                __uint_as_float(d1[c4 * 4 + 0]), __uint_as_float(d1[c4 * 4 + 1]),
                __uint_as_float(d1[c4 * 4 + 2]), __uint_as_float(d1[c4 * 4 + 3]));
        }
    }
    __syncthreads();
#else
    // ---------------- SIMT fallback (base-arch pass only; never selected) --
    (void)sb; (void)tmem; (void)committed; (void)waited;
    float acc[64];
    #pragma unroll
    for (int j = 0; j < 64; j++) acc[j] = 0.f;
    for (int c = c0; c < c1; c++) {
        const float* Ap; int la;
        const float* Bp; int lb;
        if (c < splitc) { Ap = A0 + c * 64;            la = lda0;
                          Bp = B0 + c * 64;            lb = ldb0; }
        else            { Ap = A1 + (c - splitc) * 64; la = lda1;
                          Bp = B1 + (c - splitc) * 64; lb = ldb1; }
        for (int i = tid; i < 1024; i += NTH) {
            int r = i >> 4, c4 = i & 15;
            *reinterpret_cast<float4*>(smf + r * 64 + c4 * 4) =
                *reinterpret_cast<const float4*>(Bp + (size_t)r * lb + c4 * 4);
        }
        __syncthreads();
        if (tid < 128) {
            const float* arow = Ap + (size_t)tid * la;
            for (int k = 0; k < 64; k++) {
                float a = arow[k];
                #pragma unroll
                for (int j = 0; j < 64; j++) acc[j] += a * smf[j * 64 + k];
            }
        }
        __syncthreads();
    }
    if (tid < 128) {
        float* drow = dst + (size_t)tid * ldd;
        #pragma unroll
        for (int j = 0; j < 64; j += 4)
            *reinterpret_cast<float4*>(drow + j) =
                make_float4(acc[j], acc[j + 1], acc[j + 2], acc[j + 3]);
    }
    __syncthreads();
#endif
}

// ---------------------------------------------------------------------------
__global__ void __launch_bounds__(NTH, 1) k_rnn(
    const float* __restrict__ x,
    const float* __restrict__ Wih1, const float* __restrict__ bih1,
    const float* __restrict__ Whh1, const float* __restrict__ bhh1,
    const float* __restrict__ Wih2, const float* __restrict__ bih2,
    const float* __restrict__ Whh2, const float* __restrict__ bhh2,
    const float* __restrict__ Wg,   const float* __restrict__ bg,
    const float* __restrict__ Wo1,  const float* __restrict__ bo1,
    const float* __restrict__ Wo2,  const float* __restrict__ bo2,
    float* __restrict__ out)
{
    extern __shared__ char dynsm[];
    const uint32_t sb = cvta_s(dynsm);
    float* smf = reinterpret_cast<float*>(dynsm);
    const int tid = threadIdx.x;
    const int u = blockIdx.x;
    unsigned epoch = g_epoch_base;           // continue across launches
    uint32_t committed[2] = {0u, 0u}, waited[2] = {0u, 0u};
    uint32_t tmem = 0;

#if HAS_TCGEN05
    if (tid < 32) {
        asm volatile(
            "tcgen05.alloc.cta_group::1.sync.aligned.shared::cta.b32 [%0], %1;"
            :: "r"(sb), "r"(64u) : "memory");
        asm volatile("tcgen05.relinquish_alloc_permit.cta_group::1.sync.aligned;");
    }
    if (tid == 0) {
        asm volatile("mbarrier.init.shared.b64 [%0], 1;" :: "r"(sb + 8) : "memory");
        asm volatile("mbarrier.init.shared.b64 [%0], 1;" :: "r"(sb + 16) : "memory");
    }
    __syncthreads();
    asm volatile("ld.shared.b32 %0, [%1];" : "=r"(tmem) : "r"(sb));
#endif

    const int n4 = BB * HH / 4;   // 32768 float4

    // ---- state init (re-done each launch; replay-safe) ----
    for (int i = u * NTH + tid; i < BB * HH; i += NCTA * NTH) {
        bufH1[i] = 0.f; bufH2[i] = 0.f; g_u[i] = 1.f;
    }
    gsync(epoch, u, tid);

    for (int t = 0; t <= TT; t++) {
        // ===== phase 1: all GEMMs depending on h1(t-1), h2(t-1), x(t) =====
        if (u < 48 && t < TT) {
            // T1: h1pre = x(t)@Wih1^T + h1@Whh1^T  (17 chunks, 3 slices)
            int jt = u / 3, s = u % 3;
            int c0 = (s == 0) ? 0 : (s == 1 ? 6 : 12);
            int c1 = (s == 0) ? 6 : (s == 1 ? 12 : 17);
            run_unit(c0, c1, 1,
                     x + (size_t)t * 64, TT * II, bufH1, HH,
                     Wih1 + (size_t)jt * 64 * II, II,
                     Whh1 + (size_t)jt * 64 * HH, HH,
                     sb, smf, tmem,
                     pH1 + (size_t)s * BB * HH + jt * 64, HH,
                     tid, committed, waited);
        } else if (u < 96 && t < TT) {
            // T2: h2@Wg2^T (second half of Wg)  (16 chunks, 3 slices)
            int idx = u - 48, jt = idx / 3, s = idx % 3;
            int c0 = (s == 0) ? 0 : (s == 1 ? 6 : 11);
            int c1 = (s == 0) ? 6 : (s == 1 ? 11 : 16);
            run_unit(c0, c1, 0, nullptr, 0, bufH2, HH, nullptr, 0,
                     Wg + (size_t)jt * 64 * 2048 + 1024, 2048,
                     sb, smf, tmem,
                     pG + (size_t)s * BB * HH + jt * 64, HH,
                     tid, committed, waited);
        } else if (u < 144 && t < TT) {
            // T3: h2@Whh2^T  (16 chunks, 3 slices)
            int idx = u - 96, jt = idx / 3, s = idx % 3;
            int c0 = (s == 0) ? 0 : (s == 1 ? 6 : 11);
            int c1 = (s == 0) ? 6 : (s == 1 ? 11 : 16);
            run_unit(c0, c1, 0, nullptr, 0, bufH2, HH, nullptr, 0,
                     Whh2 + (size_t)jt * 64 * HH, HH,
                     sb, smf, tmem,
                     pH2 + (size_t)s * BB * HH + jt * 64, HH,
                     tid, committed, waited);
        } else if (u >= 144 && u < 147) {
            // T4: h2@Wo2^T  (runs at every t incl. t==TT for out(TT-1))
            int s = u - 144;
            int c0 = (s == 0) ? 0 : (s == 1 ? 6 : 11);
            int c1 = (s == 0) ? 6 : (s == 1 ? 11 : 16);
            run_unit(c0, c1, 0, nullptr, 0, bufH2, HH, nullptr, 0,
                     Wo2, HH,
                     sb, smf, tmem,
                     pO + (size_t)s * BB * OO, OO,
                     tid, committed, waited);
        }
        gsync(epoch, u, tid);

        // ===== reduce 1: h1(t); u(t-1); out(t-1) =====
        if (t < TT) {
            for (int i4 = u * NTH + tid; i4 < n4; i4 += NCTA * NTH) {
                int j0 = (i4 << 2) & (HH - 1);
                float4 b1 = *reinterpret_cast<const float4*>(bih1 + j0);
                float4 b2 = *reinterpret_cast<const float4*>(bhh1 + j0);
                float4 s = make_float4(b1.x + b2.x, b1.y + b2.y,
                                       b1.z + b2.z, b1.w + b2.w);
                #pragma unroll
                for (int ss = 0; ss < 3; ss++) {
                    float4 p = reinterpret_cast<const float4*>(pH1)[ss * n4 + i4];
                    s.x += p.x; s.y += p.y; s.z += p.z; s.w += p.w;
                }
                reinterpret_cast<float4*>(bufH1)[i4] =
                    make_float4(tanhf(s.x), tanhf(s.y), tanhf(s.z), tanhf(s.w));
            }
        }
        if (t > 0 && t < TT) {
            for (int i4 = u * NTH + tid; i4 < n4; i4 += NCTA * NTH) {
                int j0 = (i4 << 2) & (HH - 1);
                float4 s = *reinterpret_cast<const float4*>(bg + j0);
                #pragma unroll
                for (int ss = 0; ss < 7; ss++) {
                    float4 p = reinterpret_cast<const float4*>(pG)[ss * n4 + i4];
                    s.x += p.x; s.y += p.y; s.z += p.z; s.w += p.w;
                }
                float4 r;
                r.x = 1.f / (1.f + expf(-s.x));
                r.y = 1.f / (1.f + expf(-s.y));
                r.z = 1.f / (1.f + expf(-s.z));
                r.w = 1.f / (1.f + expf(-s.w));
                reinterpret_cast<float4*>(g_u)[i4] = r;
            }
        }
        if (t > 0) {
            for (int i4 = u * NTH + tid; i4 < BB * OO / 4; i4 += NCTA * NTH) {
                int b = i4 >> 4;
                int o4 = (i4 & 15) * 4;
                float4 s1 = *reinterpret_cast<const float4*>(bo1 + o4);
                float4 s2 = *reinterpret_cast<const float4*>(bo2 + o4);
                #pragma unroll
                for (int ss = 3; ss < 7; ss++) {
                    float4 p = *reinterpret_cast<const float4*>(
                        pO + (size_t)ss * BB * OO + b * OO + o4);
                    s1.x += p.x; s1.y += p.y; s1.z += p.z; s1.w += p.w;
                }
                #pragma unroll
                for (int ss = 0; ss < 3; ss++) {
                    float4 p = *reinterpret_cast<const float4*>(
                        pO + (size_t)ss * BB * OO + b * OO + o4);
                    s2.x += p.x; s2.y += p.y; s2.z += p.z; s2.w += p.w;
                }
                float4 r;
                r.x = tanhf(s1.x) + tanhf(s2.x);
                r.y = tanhf(s1.y) + tanhf(s2.y);
                r.z = tanhf(s1.z) + tanhf(s2.z);
                r.w = tanhf(s1.w) + tanhf(s2.w);
                *reinterpret_cast<float4*>(
                    out + (size_t)b * TT * OO + (t - 1) * OO + o4) = r;
            }
        }
        if (t == TT) break;
        gsync(epoch, u, tid);

        // ===== phase 2: all GEMMs depending on h1(t) =====
        if (u < 64) {
            // T5: h1@Wih2^T  (16 chunks, 4 slices)
            int jt = u >> 2, s = u & 3;
            run_unit(s * 4, s * 4 + 4, 0, nullptr, 0, bufH1, HH, nullptr, 0,
                     Wih2 + (size_t)jt * 64 * HH, HH,
                     sb, smf, tmem,
                     pH2 + (size_t)(3 + s) * BB * HH + jt * 64, HH,
                     tid, committed, waited);
        } else if (u < 128) {
            // T6: h1@Wg1^T (first half of Wg)
            int idx = u - 64, jt = idx >> 2, s = idx & 3;
            run_unit(s * 4, s * 4 + 4, 0, nullptr, 0, bufH1, HH, nullptr, 0,
                     Wg + (size_t)jt * 64 * 2048, 2048,
                     sb, smf, tmem,
                     pG + (size_t)(3 + s) * BB * HH + jt * 64, HH,
                     tid, committed, waited);
        } else if (u < 132) {
            // T7: h1@Wo1^T
            int s = u - 128;
            run_unit(s * 4, s * 4 + 4, 0, nullptr, 0, bufH1, HH, nullptr, 0,
                     Wo1, HH,
                     sb, smf, tmem,
                     pO + (size_t)(3 + s) * BB * OO, OO,
                     tid, committed, waited);
        }
        gsync(epoch, u, tid);

        // ===== reduce 2: h2(t) = u(t-1)*tanh(.) + (1-u(t-1))*h2(t-1) =====
        for (int i4 = u * NTH + tid; i4 < n4; i4 += NCTA * NTH) {
            int j0 = (i4 << 2) & (HH - 1);
            float4 b1 = *reinterpret_cast<const float4*>(bih2 + j0);
            float4 b2 = *reinterpret_cast<const float4*>(bhh2 + j0);
            float4 s = make_float4(b1.x + b2.x, b1.y + b2.y,
                                   b1.z + b2.z, b1.w + b2.w);
            #pragma unroll
            for (int ss = 0; ss < 7; ss++) {
                float4 p = reinterpret_cast<const float4*>(pH2)[ss * n4 + i4];
                s.x += p.x; s.y += p.y; s.z += p.z; s.w += p.w;
            }
            float4 uu = reinterpret_cast<const float4*>(g_u)[i4];
            float4 hp = reinterpret_cast<const float4*>(bufH2)[i4];
            float4 r;
            r.x = uu.x * tanhf(s.x) + (1.f - uu.x) * hp.x;
            r.y = uu.y * tanhf(s.y) + (1.f - uu.y) * hp.y;
            r.z = uu.z * tanhf(s.z) + (1.f - uu.z) * hp.z;
            r.w = uu.w * tanhf(s.w) + (1.f - uu.w) * hp.w;
            reinterpret_cast<float4*>(bufH2)[i4] = r;
        }
        gsync(epoch, u, tid);
    }

    // persist epoch for next launch (all CTAs computed the same count)
    if (u == 0 && tid == 0) g_epoch_base = epoch;

    __syncthreads();
#if HAS_TCGEN05
    if (tid < 32) {
        asm volatile("tcgen05.dealloc.cta_group::1.sync.aligned.b32 %0, %1;"
                     :: "r"(tmem), "r"(64u));
    }
#endif
}

// ---------------------------------------------------------------------------
extern "C" void kernel_launch(void* const* d_in, const int* in_sizes, int n_in,
                              void* d_out, int out_size) {
    const float* x    = (const float*)d_in[0];
    const float* Wih1 = (const float*)d_in[1];
    const float* bih1 = (const float*)d_in[2];
    const float* Whh1 = (const float*)d_in[3];
    const float* bhh1 = (const float*)d_in[4];
    const float* Wih2 = (const float*)d_in[5];
    const float* bih2 = (const float*)d_in[6];
    const float* Whh2 = (const float*)d_in[7];
    const float* bhh2 = (const float*)d_in[8];
    const float* Wg   = (const float*)d_in[9];
    const float* bg   = (const float*)d_in[10];
    const float* Wo1  = (const float*)d_in[11];
    const float* bo1  = (const float*)d_in[12];
    const float* Wo2  = (const float*)d_in[13];
    const float* bo2  = (const float*)d_in[14];
    float* out = (float*)d_out;

    cudaFuncSetAttribute(k_rnn, cudaFuncAttributeMaxDynamicSharedMemorySize,
                         SMEM_BYTES);

    k_rnn<<<NCTA, NTH, SMEM_BYTES>>>(x, Wih1, bih1, Whh1, bhh1,
                                     Wih2, bih2, Whh2, bhh2,
                                     Wg, bg, Wo1, bo1, Wo2, bo2, out);
}

// round 13
// speedup vs baseline: 1.7311x; 1.0259x over previous
#include <cuda_runtime.h>
#include <cstdint>

#define BB 128
#define TT 256
#define II 64
#define HH 1024
#define OO 64
#define NCTA 148
#define NTH 256

#if defined(__CUDA_ARCH_FEAT_SM103_ALL) || defined(__CUDA_ARCH_SPECIFIC__)
#define HAS_TCGEN05 1
#else
#define HAS_TCGEN05 0
#endif

// idesc: dtype=F32(1<<4), atype=TF32(2<<7), btype=TF32(2<<10), N/8=8<<17, M/16=8<<24
#define IDESC_TF32 0x8100910u

// smem: [0]=tmem ptr, [8]=mbar0, [16]=mbar1
// buffer b at 1024 + b*98304: Ahi +0, Alo +32768, Bhi +65536, Blo +81920
#define SMEM_BYTES 197632

// ---------------- persistent device globals (zero-initialized) -------------
__device__ float bufH1[BB * HH];       // h1 [b][j]
__device__ float bufH2[BB * HH];       // h2 [b][j]
__device__ float g_u[BB * HH];         // gate [b][j]
__device__ float pH1[3 * BB * HH];     // h1pre slices
__device__ float pH2[7 * BB * HH];     // h2pre slices (0-2: Whh2*h2, 3-6: Wih2*h1)
__device__ float pG [7 * BB * HH];     // gate slices  (0-2: Wg2*h2,  3-6: Wg1*h1)
__device__ float pO [7 * BB * OO];     // out slices   (0-2: Wo2*h2,  3-6: Wo1*h1)
__device__ volatile unsigned g_flags[NCTA * 32];  // barrier flags (128B stride)
__device__ unsigned g_epoch_base;                 // persists across launches

// ---------------------------------------------------------------------------
__device__ __forceinline__ uint32_t cvta_s(const void* p) {
    uint32_t a;
    asm("{ .reg .u64 t; cvta.to.shared.u64 t, %1; cvt.u32.u64 %0, t; }"
        : "=r"(a) : "l"(p));
    return a;
}

__device__ __forceinline__ bool elect1() {
    uint32_t p;
    asm volatile("{ .reg .pred p; elect.sync _|p, 0xFFFFFFFF; selp.b32 %0, 1, 0, p; }"
                 : "=r"(p));
    return p != 0;
}

__device__ __forceinline__ uint64_t sdesc(uint32_t addr) {
    // SW128 (2<<61) | version(1<<46) | SBO=64<<32 | LBO=1<<16
    return 0x4000404000010000ull | ((uint64_t)(addr >> 4) & 0x3FFF);
}

__device__ __forceinline__ void mbar_wait(uint32_t mbar, uint32_t parity) {
    asm volatile(
        "{\n\t.reg .pred P;\n\t"
        "WL%=:\n\t"
        "mbarrier.try_wait.parity.acquire.cta.shared::cta.b64 P, [%0], %1, 0x989680;\n\t"
        "@!P bra WL%=;\n\t}"
        :: "r"(mbar), "r"(parity) : "memory");
}

// Distributed-flag grid barrier (epochs continue across launches).
__device__ __forceinline__ void gsync(unsigned &epoch, int u, int tid) {
    __syncthreads();
    epoch++;
    __threadfence();
    if (tid == 0) g_flags[u * 32] = epoch;
    for (int i = tid; i < NCTA; i += NTH)
        while (g_flags[i * 32] < epoch) { }
    __syncthreads();
    __threadfence();
}

// exact hi/lo split: hi = tf32 truncation (exact), lo = x - hi (exact)
__device__ __forceinline__ void split_f4(float4 v, float4 &hi, float4 &lo) {
    hi.x = __uint_as_float(__float_as_uint(v.x) & 0xFFFFE000u); lo.x = v.x - hi.x;
    hi.y = __uint_as_float(__float_as_uint(v.y) & 0xFFFFE000u); lo.y = v.y - hi.y;
    hi.z = __uint_as_float(__float_as_uint(v.z) & 0xFFFFE000u); lo.z = v.z - hi.z;
    hi.w = __uint_as_float(__float_as_uint(v.w) & 0xFFFFE000u); lo.w = v.w - hi.w;
}

#if HAS_TCGEN05
#define LDTM32(r, a) \
    asm volatile( \
        "tcgen05.ld.sync.aligned.32x32b.x32.b32 " \
        "{%0, %1, %2, %3, %4, %5, %6, %7, " \
        " %8, %9, %10, %11, %12, %13, %14, %15, " \
        " %16, %17, %18, %19, %20, %21, %22, %23, " \
        " %24, %25, %26, %27, %28, %29, %30, %31}, [%32];" \
        : "=r"((r)[0]),  "=r"((r)[1]),  "=r"((r)[2]),  "=r"((r)[3]), \
          "=r"((r)[4]),  "=r"((r)[5]),  "=r"((r)[6]),  "=r"((r)[7]), \
          "=r"((r)[8]),  "=r"((r)[9]),  "=r"((r)[10]), "=r"((r)[11]), \
          "=r"((r)[12]), "=r"((r)[13]), "=r"((r)[14]), "=r"((r)[15]), \
          "=r"((r)[16]), "=r"((r)[17]), "=r"((r)[18]), "=r"((r)[19]), \
          "=r"((r)[20]), "=r"((r)[21]), "=r"((r)[22]), "=r"((r)[23]), \
          "=r"((r)[24]), "=r"((r)[25]), "=r"((r)[26]), "=r"((r)[27]), \
          "=r"((r)[28]), "=r"((r)[29]), "=r"((r)[30]), "=r"((r)[31]) \
        : "r"(a))

__device__ __forceinline__ void mma_tf32(uint32_t tmem, uint64_t a, uint64_t b,
                                         uint32_t en) {
    asm volatile(
        "{\n\t.reg .pred p;\n\t"
        "setp.ne.u32 p, %4, 0;\n\t"
        "tcgen05.mma.cta_group::1.kind::tf32 [%0], %1, %2, %3, "
        "{%5, %5, %5, %5}, p;\n\t}"
        :: "r"(tmem), "l"(a), "l"(b), "r"(IDESC_TF32), "r"(en), "r"(0u)
        : "memory");
}
#endif

// ---------------------------------------------------------------------------
// Resolve + batched-load one chunk's operands into registers (high MLP).
// A (activations / x): streaming, cross-CTA-mutable -> __ldcg.
// B (weights): read-only -> default.
__device__ __forceinline__ void ldg_chunk(
    int c, int splitc,
    const float* __restrict__ A0, int lda0,
    const float* __restrict__ A1, int lda1,
    const float* __restrict__ B0, int ldb0,
    const float* __restrict__ B1, int ldb1,
    int tid, float4 (&va)[8], float4 (&vb)[4])
{
    const float* Ap; int la;
    const float* Bp; int lb;
    if (c < splitc) { Ap = A0 + c * 64;            la = lda0;
                      Bp = B0 + c * 64;            lb = ldb0; }
    else            { Ap = A1 + (c - splitc) * 64; la = lda1;
                      Bp = B1 + (c - splitc) * 64; lb = ldb1; }
    #pragma unroll
    for (int r = 0; r < 8; r++) {               // A: 2048 float4 / 256
        int i = tid + r * NTH;
        int rr = i >> 4, c4 = i & 15;
        va[r] = __ldcg(reinterpret_cast<const float4*>(Ap + (size_t)rr * la + c4 * 4));
    }
    #pragma unroll
    for (int r = 0; r < 4; r++) {               // B: 1024 float4 / 256
        int i = tid + r * NTH;
        int rr = i >> 4, c4 = i & 15;
        vb[r] = *reinterpret_cast<const float4*>(Bp + (size_t)rr * lb + c4 * 4);
    }
}

// ---------------------------------------------------------------------------
// One split-K unit: D[b=128][64 j] += A[128 x 64k-chunks] @ B[64 x ...]^T
// in 3xTF32 over absolute chunk range [c0,c1). Chunks with index < splitc
// come from (A0,lda0)/(B0,ldb0), the rest from (A1,lda1)/(B1,ldb1).
// Software-pipelined: chunk c's LDGs issue at end of iteration c-1,
// overlapping MMA(c-1); STS consumes registers; double-buffered smem.
__device__ __forceinline__ void run_unit(
    int c0, int c1, int splitc,
    const float* __restrict__ A0, int lda0,
    const float* __restrict__ A1, int lda1,
    const float* __restrict__ B0, int ldb0,
    const float* __restrict__ B1, int ldb1,
    uint32_t sb, float* __restrict__ smf, uint32_t tmem,
    float* __restrict__ dst, int ldd,
    int tid, uint32_t* committed, uint32_t* waited)
{
#if HAS_TCGEN05
    (void)smf;
    float4 va[8], vb[4];
    ldg_chunk(c0, splitc, A0, lda0, A1, lda1, B0, ldb0, B1, ldb1, tid, va, vb);

    for (int c = c0; c < c1; c++) {
        const int b = (c - c0) & 1;
        const uint32_t mbar = sb + 8 + b * 8;
        if (committed[b] > waited[b]) {          // buffer owned by MMA c-2
            mbar_wait(mbar, waited[b] & 1);
            waited[b]++;
        }
        const uint32_t sA = sb + 1024 + b * 98304;
        const uint32_t sB = sA + 65536;

        // ---- STS current chunk from registers (split hi/lo) ----
        #pragma unroll
        for (int r = 0; r < 8; r++) {
            int i = tid + r * NTH;
            int rr = i >> 4, c4 = i & 15;
            float4 hi, lo;
            split_f4(va[r], hi, lo);
            int bo = (((c4 >> 3) * 16 + (rr >> 3)) << 10) | ((rr & 7) << 7) | ((c4 & 7) << 4);
            uint32_t sw = bo ^ ((bo >> 3) & 0x70);
            asm volatile("st.shared.v4.b32 [%0], {%1,%2,%3,%4};"
                :: "r"(sA + sw), "r"(__float_as_uint(hi.x)),
                   "r"(__float_as_uint(hi.y)), "r"(__float_as_uint(hi.z)),
                   "r"(__float_as_uint(hi.w)) : "memory");
            asm volatile("st.shared.v4.b32 [%0], {%1,%2,%3,%4};"
                :: "r"(sA + 32768 + sw), "r"(__float_as_uint(lo.x)),
                   "r"(__float_as_uint(lo.y)), "r"(__float_as_uint(lo.z)),
                   "r"(__float_as_uint(lo.w)) : "memory");
        }
        #pragma unroll
        for (int r = 0; r < 4; r++) {
            int i = tid + r * NTH;
            int rr = i >> 4, c4 = i & 15;
            float4 hi, lo;
            split_f4(vb[r], hi, lo);
            int bo = (((c4 >> 3) * 8 + (rr >> 3)) << 10) | ((rr & 7) << 7) | ((c4 & 7) << 4);
            uint32_t sw = bo ^ ((bo >> 3) & 0x70);
            asm volatile("st.shared.v4.b32 [%0], {%1,%2,%3,%4};"
                :: "r"(sB + sw), "r"(__float_as_uint(hi.x)),
                   "r"(__float_as_uint(hi.y)), "r"(__float_as_uint(hi.z)),
                   "r"(__float_as_uint(hi.w)) : "memory");
            asm volatile("st.shared.v4.b32 [%0], {%1,%2,%3,%4};"
                :: "r"(sB + 16384 + sw), "r"(__float_as_uint(lo.x)),
                   "r"(__float_as_uint(lo.y)), "r"(__float_as_uint(lo.z)),
                   "r"(__float_as_uint(lo.w)) : "memory");
        }
        asm volatile("fence.proxy.async.shared::cta;" ::: "memory");
        __syncthreads();

        // ---- prefetch next chunk (overlaps MMA below + next mbar wait) ----
        if (c + 1 < c1)
            ldg_chunk(c + 1, splitc, A0, lda0, A1, lda1, B0, ldb0, B1, ldb1,
                      tid, va, vb);

        if (tid < 32 && elect1()) {
            uint64_t dahi = sdesc(sA), dalo = sdesc(sA + 32768);
            uint64_t dbhi = sdesc(sB), dblo = sdesc(sB + 16384);
            #pragma unroll
            for (int s = 0; s < 8; s++) {
                uint64_t oa = (uint64_t)(((s >> 2) << 10) + ((s & 3) << 1));
                uint64_t ob = (uint64_t)(((s >> 2) << 9) + ((s & 3) << 1));
                mma_tf32(tmem, dahi + oa, dbhi + ob, (c > c0 || s > 0) ? 1u : 0u);
                mma_tf32(tmem, dahi + oa, dblo + ob, 1u);
                mma_tf32(tmem, dalo + oa, dbhi + ob, 1u);
            }
            asm volatile(
                "tcgen05.commit.cta_group::1.mbarrier::arrive::one.shared::cluster.b64 [%0];"
                :: "r"(mbar) : "memory");
        }
        committed[b]++;
    }
    #pragma unroll
    for (int b = 0; b < 2; b++) {
        if (committed[b] > waited[b]) {
            mbar_wait(sb + 8 + b * 8, waited[b] & 1);
            waited[b]++;
        }
    }
    asm volatile("tcgen05.fence::after_thread_sync;" ::: "memory");

    if (tid < 128) {
        uint32_t d0[32], d1[32];
        LDTM32(d0, tmem);
        LDTM32(d1, tmem + 32);
        asm volatile("tcgen05.wait::ld.sync.aligned;" ::: "memory");
        asm volatile("tcgen05.fence::before_thread_sync;" ::: "memory");

        float* drow = dst + (size_t)tid * ldd;       // row b == tid
        #pragma unroll
        for (int c4 = 0; c4 < 8; c4++) {
            *reinterpret_cast<float4*>(drow + c4 * 4) = make_float4(
                __uint_as_float(d0[c4 * 4 + 0]), __uint_as_float(d0[c4 * 4 + 1]),
                __uint_as_float(d0[c4 * 4 + 2]), __uint_as_float(d0[c4 * 4 + 3]));
            *reinterpret_cast<float4*>(drow + 32 + c4 * 4) = make_float4(
                __uint_as_float(d1[c4 * 4 + 0]), __uint_as_float(d1[c4 * 4 + 1]),
                __uint_as_float(d1[c4 * 4 + 2]), __uint_as_float(d1[c4 * 4 + 3]));
        }
    }
    __syncthreads();
#else
    // ---------------- SIMT fallback (base-arch pass only; never selected) --
    (void)sb; (void)tmem; (void)committed; (void)waited;
    float acc[64];
    #pragma unroll
    for (int j = 0; j < 64; j++) acc[j] = 0.f;
    for (int c = c0; c < c1; c++) {
        const float* Ap; int la;
        const float* Bp; int lb;
        if (c < splitc) { Ap = A0 + c * 64;            la = lda0;
                          Bp = B0 + c * 64;            lb = ldb0; }
        else            { Ap = A1 + (c - splitc) * 64; la = lda1;
                          Bp = B1 + (c - splitc) * 64; lb = ldb1; }
        for (int i = tid; i < 1024; i += NTH) {
            int r = i >> 4, c4 = i & 15;
            *reinterpret_cast<float4*>(smf + r * 64 + c4 * 4) =
                *reinterpret_cast<const float4*>(Bp + (size_t)r * lb + c4 * 4);
        }
        __syncthreads();
        if (tid < 128) {
            const float* arow = Ap + (size_t)tid * la;
            for (int k = 0; k < 64; k++) {
                float a = arow[k];
                #pragma unroll
                for (int j = 0; j < 64; j++) acc[j] += a * smf[j * 64 + k];
            }
        }
        __syncthreads();
    }
    if (tid < 128) {
        float* drow = dst + (size_t)tid * ldd;
        #pragma unroll
        for (int j = 0; j < 64; j += 4)
            *reinterpret_cast<float4*>(drow + j) =
                make_float4(acc[j], acc[j + 1], acc[j + 2], acc[j + 3]);
    }
    __syncthreads();
#endif
}

// ---------------------------------------------------------------------------
__global__ void __launch_bounds__(NTH, 1) k_rnn(
    const float* __restrict__ x,
    const float* __restrict__ Wih1, const float* __restrict__ bih1,
    const float* __restrict__ Whh1, const float* __restrict__ bhh1,
    const float* __restrict__ Wih2, const float* __restrict__ bih2,
    const float* __restrict__ Whh2, const float* __restrict__ bhh2,
    const float* __restrict__ Wg,   const float* __restrict__ bg,
    const float* __restrict__ Wo1,  const float* __restrict__ bo1,
    const float* __restrict__ Wo2,  const float* __restrict__ bo2,
    float* __restrict__ out)
{
    extern __shared__ char dynsm[];
    const uint32_t sb = cvta_s(dynsm);
    float* smf = reinterpret_cast<float*>(dynsm);
    const int tid = threadIdx.x;
    const int u = blockIdx.x;
    unsigned epoch = g_epoch_base;           // continue across launches
    uint32_t committed[2] = {0u, 0u}, waited[2] = {0u, 0u};
    uint32_t tmem = 0;

#if HAS_TCGEN05
    if (tid < 32) {
        asm volatile(
            "tcgen05.alloc.cta_group::1.sync.aligned.shared::cta.b32 [%0], %1;"
            :: "r"(sb), "r"(64u) : "memory");
        asm volatile("tcgen05.relinquish_alloc_permit.cta_group::1.sync.aligned;");
    }
    if (tid == 0) {
        asm volatile("mbarrier.init.shared.b64 [%0], 1;" :: "r"(sb + 8) : "memory");
        asm volatile("mbarrier.init.shared.b64 [%0], 1;" :: "r"(sb + 16) : "memory");
    }
    __syncthreads();
    asm volatile("ld.shared.b32 %0, [%1];" : "=r"(tmem) : "r"(sb));
#endif

    const int n4 = BB * HH / 4;   // 32768 float4

    // ---- state init (re-done each launch; replay-safe) ----
    for (int i = u * NTH + tid; i < BB * HH; i += NCTA * NTH) {
        bufH1[i] = 0.f; bufH2[i] = 0.f; g_u[i] = 1.f;
    }
    gsync(epoch, u, tid);

    for (int t = 0; t <= TT; t++) {
        // ===== phase 1: all GEMMs depending on h1(t-1), h2(t-1), x(t) =====
        if (u < 48 && t < TT) {
            // T1: h1pre = x(t)@Wih1^T + h1@Whh1^T  (17 chunks, 3 slices)
            int jt = u / 3, s = u % 3;
            int c0 = (s == 0) ? 0 : (s == 1 ? 6 : 12);
            int c1 = (s == 0) ? 6 : (s == 1 ? 12 : 17);
            run_unit(c0, c1, 1,
                     x + (size_t)t * 64, TT * II, bufH1, HH,
                     Wih1 + (size_t)jt * 64 * II, II,
                     Whh1 + (size_t)jt * 64 * HH, HH,
                     sb, smf, tmem,
                     pH1 + (size_t)s * BB * HH + jt * 64, HH,
                     tid, committed, waited);
        } else if (u < 96 && t < TT) {
            // T2: h2@Wg2^T (second half of Wg)  (16 chunks, 3 slices)
            int idx = u - 48, jt = idx / 3, s = idx % 3;
            int c0 = (s == 0) ? 0 : (s == 1 ? 6 : 11);
            int c1 = (s == 0) ? 6 : (s == 1 ? 11 : 16);
            run_unit(c0, c1, 0, nullptr, 0, bufH2, HH, nullptr, 0,
                     Wg + (size_t)jt * 64 * 2048 + 1024, 2048,
                     sb, smf, tmem,
                     pG + (size_t)s * BB * HH + jt * 64, HH,
                     tid, committed, waited);
        } else if (u < 144 && t < TT) {
            // T3: h2@Whh2^T  (16 chunks, 3 slices)
            int idx = u - 96, jt = idx / 3, s = idx % 3;
            int c0 = (s == 0) ? 0 : (s == 1 ? 6 : 11);
            int c1 = (s == 0) ? 6 : (s == 1 ? 11 : 16);
            run_unit(c0, c1, 0, nullptr, 0, bufH2, HH, nullptr, 0,
                     Whh2 + (size_t)jt * 64 * HH, HH,
                     sb, smf, tmem,
                     pH2 + (size_t)s * BB * HH + jt * 64, HH,
                     tid, committed, waited);
        } else if (u >= 144 && u < 147) {
            // T4: h2@Wo2^T  (runs at every t incl. t==TT for out(TT-1))
            int s = u - 144;
            int c0 = (s == 0) ? 0 : (s == 1 ? 6 : 11);
            int c1 = (s == 0) ? 6 : (s == 1 ? 11 : 16);
            run_unit(c0, c1, 0, nullptr, 0, bufH2, HH, nullptr, 0,
                     Wo2, HH,
                     sb, smf, tmem,
                     pO + (size_t)s * BB * OO, OO,
                     tid, committed, waited);
        }
        gsync(epoch, u, tid);

        // ===== reduce 1: h1(t); u(t-1); out(t-1) =====
        if (t < TT) {
            for (int i4 = u * NTH + tid; i4 < n4; i4 += NCTA * NTH) {
                int j0 = (i4 << 2) & (HH - 1);
                float4 b1 = *reinterpret_cast<const float4*>(bih1 + j0);
                float4 b2 = *reinterpret_cast<const float4*>(bhh1 + j0);
                float4 s = make_float4(b1.x + b2.x, b1.y + b2.y,
                                       b1.z + b2.z, b1.w + b2.w);
                #pragma unroll
                for (int ss = 0; ss < 3; ss++) {
                    float4 p = __ldcg(&reinterpret_cast<const float4*>(pH1)[ss * n4 + i4]);
                    s.x += p.x; s.y += p.y; s.z += p.z; s.w += p.w;
                }
                reinterpret_cast<float4*>(bufH1)[i4] =
                    make_float4(tanhf(s.x), tanhf(s.y), tanhf(s.z), tanhf(s.w));
            }
        }
        if (t > 0 && t < TT) {
            for (int i4 = u * NTH + tid; i4 < n4; i4 += NCTA * NTH) {
                int j0 = (i4 << 2) & (HH - 1);
                float4 s = *reinterpret_cast<const float4*>(bg + j0);
                #pragma unroll
                for (int ss = 0; ss < 7; ss++) {
                    float4 p = __ldcg(&reinterpret_cast<const float4*>(pG)[ss * n4 + i4]);
                    s.x += p.x; s.y += p.y; s.z += p.z; s.w += p.w;
                }
                float4 r;
                r.x = 1.f / (1.f + expf(-s.x));
                r.y = 1.f / (1.f + expf(-s.y));
                r.z = 1.f / (1.f + expf(-s.z));
                r.w = 1.f / (1.f + expf(-s.w));
                reinterpret_cast<float4*>(g_u)[i4] = r;
            }
        }
        if (t > 0) {
            for (int i4 = u * NTH + tid; i4 < BB * OO / 4; i4 += NCTA * NTH) {
                int b = i4 >> 4;
                int o4 = (i4 & 15) * 4;
                float4 s1 = *reinterpret_cast<const float4*>(bo1 + o4);
                float4 s2 = *reinterpret_cast<const float4*>(bo2 + o4);
                #pragma unroll
                for (int ss = 3; ss < 7; ss++) {
                    float4 p = __ldcg(reinterpret_cast<const float4*>(
                        pO + (size_t)ss * BB * OO + b * OO + o4));
                    s1.x += p.x; s1.y += p.y; s1.z += p.z; s1.w += p.w;
                }
                #pragma unroll
                for (int ss = 0; ss < 3; ss++) {
                    float4 p = __ldcg(reinterpret_cast<const float4*>(
                        pO + (size_t)ss * BB * OO + b * OO + o4));
                    s2.x += p.x; s2.y += p.y; s2.z += p.z; s2.w += p.w;
                }
                float4 r;
                r.x = tanhf(s1.x) + tanhf(s2.x);
                r.y = tanhf(s1.y) + tanhf(s2.y);
                r.z = tanhf(s1.z) + tanhf(s2.z);
                r.w = tanhf(s1.w) + tanhf(s2.w);
                *reinterpret_cast<float4*>(
                    out + (size_t)b * TT * OO + (t - 1) * OO + o4) = r;
            }
        }
        if (t == TT) break;
        gsync(epoch, u, tid);

        // ===== phase 2: all GEMMs depending on h1(t) =====
        if (u < 64) {
            // T5: h1@Wih2^T  (16 chunks, 4 slices)
            int jt = u >> 2, s = u & 3;
            run_unit(s * 4, s * 4 + 4, 0, nullptr, 0, bufH1, HH, nullptr, 0,
                     Wih2 + (size_t)jt * 64 * HH, HH,
                     sb, smf, tmem,
                     pH2 + (size_t)(3 + s) * BB * HH + jt * 64, HH,
                     tid, committed, waited);
        } else if (u < 128) {
            // T6: h1@Wg1^T (first half of Wg)
            int idx = u - 64, jt = idx >> 2, s = idx & 3;
            run_unit(s * 4, s * 4 + 4, 0, nullptr, 0, bufH1, HH, nullptr, 0,
                     Wg + (size_t)jt * 64 * 2048, 2048,
                     sb, smf, tmem,
                     pG + (size_t)(3 + s) * BB * HH + jt * 64, HH,
                     tid, committed, waited);
        } else if (u < 132) {
            // T7: h1@Wo1^T
            int s = u - 128;
            run_unit(s * 4, s * 4 + 4, 0, nullptr, 0, bufH1, HH, nullptr, 0,
                     Wo1, HH,
                     sb, smf, tmem,
                     pO + (size_t)(3 + s) * BB * OO, OO,
                     tid, committed, waited);
        }
        gsync(epoch, u, tid);

        // ===== reduce 2: h2(t) = u(t-1)*tanh(.) + (1-u(t-1))*h2(t-1) =====
        for (int i4 = u * NTH + tid; i4 < n4; i4 += NCTA * NTH) {
            int j0 = (i4 << 2) & (HH - 1);
            float4 b1 = *reinterpret_cast<const float4*>(bih2 + j0);
            float4 b2 = *reinterpret_cast<const float4*>(bhh2 + j0);
            float4 s = make_float4(b1.x + b2.x, b1.y + b2.y,
                                   b1.z + b2.z, b1.w + b2.w);
            #pragma unroll
            for (int ss = 0; ss < 7; ss++) {
                float4 p = __ldcg(&reinterpret_cast<const float4*>(pH2)[ss * n4 + i4]);
                s.x += p.x; s.y += p.y; s.z += p.z; s.w += p.w;
            }
            float4 uu = __ldcg(&reinterpret_cast<const float4*>(g_u)[i4]);
            float4 hp = __ldcg(&reinterpret_cast<const float4*>(bufH2)[i4]);
            float4 r;
            r.x = uu.x * tanhf(s.x) + (1.f - uu.x) * hp.x;
            r.y = uu.y * tanhf(s.y) + (1.f - uu.y) * hp.y;
            r.z = uu.z * tanhf(s.z) + (1.f - uu.z) * hp.z;
            r.w = uu.w * tanhf(s.w) + (1.f - uu.w) * hp.w;
            reinterpret_cast<float4*>(bufH2)[i4] = r;
        }
        gsync(epoch, u, tid);
    }

    // persist epoch for next launch (all CTAs computed the same count)
    if (u == 0 && tid == 0) g_epoch_base = epoch;

    __syncthreads();
#if HAS_TCGEN05
    if (tid < 32) {
        asm volatile("tcgen05.dealloc.cta_group::1.sync.aligned.b32 %0, %1;"
                     :: "r"(tmem), "r"(64u));
    }
#endif
}

// ---------------------------------------------------------------------------
extern "C" void kernel_launch(void* const* d_in, const int* in_sizes, int n_in,
                              void* d_out, int out_size) {
    const float* x    = (const float*)d_in[0];
    const float* Wih1 = (const float*)d_in[1];
    const float* bih1 = (const float*)d_in[2];
    const float* Whh1 = (const float*)d_in[3];
    const float* bhh1 = (const float*)d_in[4];
    const float* Wih2 = (const float*)d_in[5];
    const float* bih2 = (const float*)d_in[6];
    const float* Whh2 = (const float*)d_in[7];
    const float* bhh2 = (const float*)d_in[8];
    const float* Wg   = (const float*)d_in[9];
    const float* bg   = (const float*)d_in[10];
    const float* Wo1  = (const float*)d_in[11];
    const float* bo1  = (const float*)d_in[12];
    const float* Wo2  = (const float*)d_in[13];
    const float* bo2  = (const float*)d_in[14];
    float* out = (float*)d_out;

    cudaFuncSetAttribute(k_rnn, cudaFuncAttributeMaxDynamicSharedMemorySize,
                         SMEM_BYTES);

    k_rnn<<<NCTA, NTH, SMEM_BYTES>>>(x, Wih1, bih1, Whh1, bhh1,
                                     Wih2, bih2, Whh2, bhh2,
                                     Wg, bg, Wo1, bo1, Wo2, bo2, out);
}